// round 14
// baseline (speedup 1.0000x reference)
#include <cuda_runtime.h>
#include <cuda_fp16.h>
#include <math.h>
#include <stdint.h>

// ---------------- problem constants ----------------
#define T_SEQ   2048
#define HID     2048
#define NUM_K   16
#define NUM_V   32
#define DK      128
#define DV      128
#define KEY_DIM 2048
#define VAL_DIM 4096
#define CONV_DIM 8192
#define QKVZ_N  12288
#define QSCALE  0.08838834764831845f

// ---------------- scratch ----------------
__device__ float  g_qkvz  [T_SEQ * QKVZ_N];
__device__ float  g_qkv   [T_SEQ * CONV_DIM];
__device__ float  g_ba    [T_SEQ * 64];
__device__ float2 g_egbeta[T_SEQ * NUM_V];
__device__ float  g_qhat  [T_SEQ * KEY_DIM];
__device__ float  g_khat  [T_SEQ * KEY_DIM];
__device__ float  g_qkdot [T_SEQ * NUM_K];
__device__ float  g_oscan [T_SEQ * VAL_DIM];

// fp16 operands: weights single fp16 (W^T), activations split hi/lo
__device__ __half g_Wq[QKVZ_N * HID];
__device__ __half g_Wo[HID * VAL_DIM];
__device__ __half g_A_hi[T_SEQ * VAL_DIM];
__device__ __half g_A_lo[T_SEQ * VAL_DIM];

// ---------------- helpers ----------------
__device__ __forceinline__ float sigmoidf_(float x) { return 1.0f / (1.0f + __expf(-x)); }
__device__ __forceinline__ float siluf_(float x)    { return x * sigmoidf_(x); }

__device__ __forceinline__ uint32_t smem_to_u32(const void* p) {
    uint32_t a;
    asm("{ .reg .u64 t; cvta.to.shared.u64 t, %1; cvt.u32.u64 %0, t; }" : "=r"(a) : "l"(p));
    return a;
}
__device__ __forceinline__ void ldsm4(uint32_t& r0, uint32_t& r1, uint32_t& r2, uint32_t& r3,
                                      uint32_t addr) {
    asm volatile("ldmatrix.sync.aligned.m8n8.x4.shared.b16 {%0,%1,%2,%3}, [%4];"
                 : "=r"(r0), "=r"(r1), "=r"(r2), "=r"(r3) : "r"(addr));
}
__device__ __forceinline__ void mma16816(float* d, const uint32_t* a, const uint32_t* b) {
    asm volatile("mma.sync.aligned.m16n8k16.row.col.f32.f16.f16.f32 "
                 "{%0,%1,%2,%3}, {%4,%5,%6,%7}, {%8,%9}, {%0,%1,%2,%3};"
                 : "+f"(d[0]), "+f"(d[1]), "+f"(d[2]), "+f"(d[3])
                 : "r"(a[0]), "r"(a[1]), "r"(a[2]), "r"(a[3]), "r"(b[0]), "r"(b[1]));
}

// ---------------- prep: fp32 -> fp16 hi/lo split ----------------
__global__ __launch_bounds__(256) void cvt_split(
    const float* __restrict__ x, __half* __restrict__ hi,
    __half* __restrict__ lo, int n4)
{
    int i = blockIdx.x * 256 + threadIdx.x;
    if (i >= n4) return;
    float4 v = ((const float4*)x)[i];
    __half h0 = __float2half_rn(v.x), h1 = __float2half_rn(v.y);
    __half h2 = __float2half_rn(v.z), h3 = __float2half_rn(v.w);
    __half l0 = __float2half_rn(v.x - __half2float(h0));
    __half l1 = __float2half_rn(v.y - __half2float(h1));
    __half l2 = __float2half_rn(v.z - __half2float(h2));
    __half l3 = __float2half_rn(v.w - __half2float(h3));
    union { __half2 h2v[2]; uint2 u; } H, L;
    H.h2v[0] = __halves2half2(h0, h1); H.h2v[1] = __halves2half2(h2, h3);
    L.h2v[0] = __halves2half2(l0, l1); L.h2v[1] = __halves2half2(l2, l3);
    ((uint2*)hi)[i] = H.u;
    ((uint2*)lo)[i] = L.u;
}

// ---------------- prep: W [K][N] fp32 -> W^T [N][K] fp16 ----------------
__global__ __launch_bounds__(256) void tr_half(
    const float* __restrict__ W, __half* __restrict__ out, int K, int N)
{
    __shared__ float t[32][33];
    int n0 = blockIdx.x * 32, k0 = blockIdx.y * 32;
    int tx = threadIdx.x, ty = threadIdx.y;
#pragma unroll
    for (int j = 0; j < 4; ++j)
        t[ty + j * 8][tx] = W[(size_t)(k0 + ty + j * 8) * N + n0 + tx];
    __syncthreads();
#pragma unroll
    for (int j = 0; j < 4; ++j) {
        int n = ty + j * 8;
        out[(size_t)(n0 + n) * K + k0 + tx] = __float2half_rn(t[tx][n]);
    }
}

// ---------------- mma.sync GEMM: 128x128 CTA, 256 threads, BK=64, 2-stage, 2 CTA/SM ----------------
#define SSTR   144
#define SZ_A   (128 * SSTR)
#define SZ_B   (128 * SSTR)
#define BUF_SZ (2 * SZ_A + SZ_B)
#define GT_SMEM (2 * BUF_SZ)

template<int ITERS>
__device__ __forceinline__ void cpa_stage(uint32_t sdst, const char* g, int Kb, int tid) {
#pragma unroll
    for (int i = 0; i < ITERS; ++i) {
        int idx = tid + i * 256;
        int row = idx >> 3;
        int q   = (idx & 7) << 4;
        uint32_t d = sdst + row * SSTR + q;
        const char* s = g + (size_t)row * Kb + q;
        asm volatile("cp.async.cg.shared.global [%0], [%1], 16;" :: "r"(d), "l"(s));
    }
}

template<int USE_LO>
__global__ __launch_bounds__(256, 2) void gemm_tc(
    const __half* __restrict__ Ahi, const __half* __restrict__ Alo,
    const __half* __restrict__ B, float* __restrict__ C, int N, int K)
{
    extern __shared__ __align__(128) char smem[];
    const uint32_t sb = smem_to_u32(smem);

    const int tid  = threadIdx.x;
    const int wid  = tid >> 5;
    const int lane = tid & 31;
    const int bm   = blockIdx.x * 128;
    const int bn   = blockIdx.y * 128;
    const int wm   = (wid >> 1) * 32;
    const int wn   = (wid & 1) * 64;
    const int Kb   = K * 2;

    const char* gAh = (const char*)(Ahi + (size_t)bm * K);
    const char* gAl = (const char*)(Alo + (size_t)bm * K);
    const char* gB  = (const char*)(B   + (size_t)bn * K);

    float acc[2][8][4];
#pragma unroll
    for (int i = 0; i < 2; ++i)
#pragma unroll
        for (int j = 0; j < 8; ++j)
#pragma unroll
            for (int r = 0; r < 4; ++r) acc[i][j][r] = 0.0f;

    const uint32_t aoff = (lane & 15) * SSTR + ((lane >> 4) << 4);
    const uint32_t boff = ((lane & 7) + ((lane >> 4) << 3)) * SSTR + (((lane >> 3) & 1) << 4);

    const int nk = K >> 6;

    {
        uint32_t sbuf = sb;
        cpa_stage<4>(sbuf,            gAh, Kb, tid);
        if (USE_LO) cpa_stage<4>(sbuf + SZ_A, gAl, Kb, tid);
        cpa_stage<4>(sbuf + 2 * SZ_A, gB,  Kb, tid);
        asm volatile("cp.async.commit_group;");
    }

    for (int kt = 0; kt < nk; ++kt) {
        asm volatile("cp.async.wait_group 0;");
        __syncthreads();

        if (kt + 1 < nk) {
            uint32_t sbuf = sb + ((kt + 1) & 1) * BUF_SZ;
            size_t ko = (size_t)(kt + 1) * 128;
            cpa_stage<4>(sbuf,            gAh + ko, Kb, tid);
            if (USE_LO) cpa_stage<4>(sbuf + SZ_A, gAl + ko, Kb, tid);
            cpa_stage<4>(sbuf + 2 * SZ_A, gB  + ko, Kb, tid);
            asm volatile("cp.async.commit_group;");
        }

        const uint32_t sAh = sb + (kt & 1) * BUF_SZ;
        const uint32_t sAl = sAh + SZ_A;
        const uint32_t sB  = sAh + 2 * SZ_A;

#pragma unroll
        for (int ks = 0; ks < 4; ++ks) {
            const uint32_t kb = ks * 32;
            uint32_t ah[2][4], al[2][4];
#pragma unroll
            for (int mt = 0; mt < 2; ++mt) {
                uint32_t base = (wm + mt * 16) * SSTR + aoff + kb;
                ldsm4(ah[mt][0], ah[mt][1], ah[mt][2], ah[mt][3], sAh + base);
                if (USE_LO)
                    ldsm4(al[mt][0], al[mt][1], al[mt][2], al[mt][3], sAl + base);
            }
#pragma unroll
            for (int pr = 0; pr < 4; ++pr) {
                uint32_t bbase = (wn + pr * 16) * SSTR + boff + kb;
                uint32_t h0, h1, h2, h3;
                ldsm4(h0, h1, h2, h3, sB + bbase);
                uint32_t b0[2] = {h0, h1}, b1[2] = {h2, h3};
#pragma unroll
                for (int mt = 0; mt < 2; ++mt) {
                    mma16816(acc[mt][2 * pr],     ah[mt], b0);
                    mma16816(acc[mt][2 * pr + 1], ah[mt], b1);
                    if (USE_LO) {
                        mma16816(acc[mt][2 * pr],     al[mt], b0);
                        mma16816(acc[mt][2 * pr + 1], al[mt], b1);
                    }
                }
            }
        }
    }

    const int g  = lane >> 2;
    const int tg = lane & 3;
#pragma unroll
    for (int mt = 0; mt < 2; ++mt) {
#pragma unroll
        for (int nt = 0; nt < 8; ++nt) {
            const float* d = acc[mt][nt];
            size_t r = (size_t)(bm + wm + mt * 16 + g) * N + bn + wn + nt * 8 + tg * 2;
            *(float2*)&C[r] = make_float2(d[0], d[1]);
            *(float2*)&C[r + 8 * (size_t)N] = make_float2(d[2], d[3]);
        }
    }
}

// ---------------- tiled small GEMM: ba = h @ W_ba (2048x64, K=2048) ----------------
__global__ __launch_bounds__(256) void gemm_ba(
    const float* __restrict__ A, const float* __restrict__ B, float* __restrict__ C)
{
    __shared__ float sh[64][65];
    __shared__ float sB[64][65];
    const int tid = threadIdx.x;
    const int col = tid & 63;
    const int rg  = tid >> 6;
    const int br  = blockIdx.x * 64;

    float acc[16];
#pragma unroll
    for (int r = 0; r < 16; ++r) acc[r] = 0.0f;

    for (int kt = 0; kt < HID / 64; ++kt) {
#pragma unroll
        for (int i = 0; i < 16; ++i) {
            int idx = tid + i * 256;
            int row = idx >> 6, kk = idx & 63;
            sh[row][kk] = A[(size_t)(br + row) * HID + kt * 64 + kk];
            sB[row][kk] = B[(size_t)(kt * 64 + row) * 64 + kk];
        }
        __syncthreads();
#pragma unroll 16
        for (int kk = 0; kk < 64; ++kk) {
            float b = sB[kk][col];
#pragma unroll
            for (int r = 0; r < 16; ++r)
                acc[r] = fmaf(sh[rg * 16 + r][kk], b, acc[r]);
        }
        __syncthreads();
    }
#pragma unroll
    for (int r = 0; r < 16; ++r)
        C[(size_t)(br + rg * 16 + r) * 64 + col] = acc[r];
}

// ---------------- causal depthwise conv (K=4) + SiLU, 4 t per thread ----------------
__global__ __launch_bounds__(256) void conv_silu(
    const float* __restrict__ qkvz, const float* __restrict__ conv_w,
    float* __restrict__ out)
{
    int idx = blockIdx.x * blockDim.x + threadIdx.x;
    if (idx >= (T_SEQ / 4) * CONV_DIM) return;
    int tq = idx >> 13;
    int c  = idx & (CONV_DIM - 1);
    int t0 = tq * 4;
    const float* w = conv_w + c * 4;
    float xv[7];
#pragma unroll
    for (int j = 0; j < 7; ++j) {
        int tt = t0 - 3 + j;
        xv[j] = (tt >= 0) ? qkvz[(size_t)tt * QKVZ_N + c] : 0.0f;
    }
#pragma unroll
    for (int i = 0; i < 4; ++i) {
        float a = w[0] * xv[i];
        a = fmaf(w[1], xv[i + 1], a);
        a = fmaf(w[2], xv[i + 2], a);
        a = fmaf(w[3], xv[i + 3], a);
        out[(size_t)(t0 + i) * CONV_DIM + c] = siluf_(a);
    }
}

// ---------------- gating ----------------
__global__ __launch_bounds__(256) void gate_prep(
    const float* __restrict__ ba, const float* __restrict__ A_log,
    const float* __restrict__ dt_bias, float2* __restrict__ egbeta)
{
    int i = blockIdx.x * blockDim.x + threadIdx.x;
    if (i >= T_SEQ * NUM_V) return;
    int t = i >> 5;
    int h = i & 31;
    float b = ba[(size_t)t * 64 + h];
    float a = ba[(size_t)t * 64 + 32 + h];
    float x = a + dt_bias[h];
    float sp = (x > 20.0f) ? x : log1pf(expf(x));
    float g = -expf(A_log[h]) * sp;
    egbeta[i] = make_float2(expf(g), sigmoidf_(b));
}

// ---------------- fused l2norm(q,k) + qk dot: one warp per (t, key-head) ----------------
__global__ __launch_bounds__(256) void l2norm_qk_dot(
    const float* __restrict__ qkv, float* __restrict__ qhat,
    float* __restrict__ khat, float* __restrict__ qkdot)
{
    int gid  = blockIdx.x * 8 + (threadIdx.x >> 5);
    int lane = threadIdx.x & 31;
    int t  = gid >> 4;
    int kh = gid & 15;
    const float* qsrc = qkv + (size_t)t * CONV_DIM + kh * DK;
    float4 q = *((const float4*)qsrc + lane);
    float4 k = *((const float4*)(qsrc + KEY_DIM) + lane);
    float sq  = q.x * q.x + q.y * q.y + q.z * q.z + q.w * q.w;
    float sk  = k.x * k.x + k.y * k.y + k.z * k.z + k.w * k.w;
    float sqk = q.x * k.x + q.y * k.y + q.z * k.z + q.w * k.w;
#pragma unroll
    for (int off = 16; off > 0; off >>= 1) {
        sq  += __shfl_xor_sync(0xffffffffu, sq,  off);
        sk  += __shfl_xor_sync(0xffffffffu, sk,  off);
        sqk += __shfl_xor_sync(0xffffffffu, sqk, off);
    }
    float rq = rsqrtf(sq + 1e-6f) * QSCALE;
    float rk = rsqrtf(sk + 1e-6f);
    size_t base = (size_t)t * KEY_DIM + kh * DK;
    *((float4*)(qhat + base) + lane) = make_float4(q.x * rq, q.y * rq, q.z * rq, q.w * rq);
    *((float4*)(khat + base) + lane) = make_float4(k.x * rk, k.y * rk, k.z * rk, k.w * rk);
    if (lane == 0) qkdot[t * NUM_K + kh] = sqk * rq * rk;
}

// ---------------- gated delta scan: smem-staged, 16 warps x 4 cols, 8 lanes/col ----------------
// CTA = (head, 64-col group); grid 64. Chunks of 32 timesteps via cp.async double buffer.
// smem per buffer: K 16384 | Q 16384 | V 8192 | EB 256 | XQ 128 -> 41472 bytes
#define SC_TC   32
#define SC_QB   16384
#define SC_VB   32768
#define SC_EB   40960
#define SC_XB   41216
#define SC_BUF  41472
#define SC_SMEM (2 * SC_BUF)

__device__ __forceinline__ void scan_stage(
    uint32_t sbase, const float* kb_, const float* qb_,
    const float* vb_, const float* eb_, const float* xb_, int tid)
{
    // k/q: plain row-major, 128 floats (512B) per tt
#pragma unroll
    for (int i = 0; i < 4; ++i) {
        int idx = tid + i * 512;          // 0..2047
        int isq = idx >> 10;
        int r   = idx & 1023;
        int tt  = r >> 5;
        int j   = r & 31;
        const float* src = (isq ? qb_ : kb_) + (size_t)tt * KEY_DIM + j * 4;
        uint32_t dst = sbase + (isq ? SC_QB : 0) + tt * 512 + j * 16;
        asm volatile("cp.async.ca.shared.global [%0], [%1], 16;" :: "r"(dst), "l"(src));
    }
    {                                     // v: 64 floats per tt = 16 float4, 512 total
        int tt = tid >> 4, j = tid & 15;
        const float* src = vb_ + (size_t)tt * CONV_DIM + j * 4;
        uint32_t dst = sbase + SC_VB + tt * 256 + j * 16;
        asm volatile("cp.async.ca.shared.global [%0], [%1], 16;" :: "r"(dst), "l"(src));
    }
    if (tid < 32) {                       // egbeta: float2 per tt
        const float* src = eb_ + (size_t)tid * (2 * NUM_V);
        uint32_t dst = sbase + SC_EB + tid * 8;
        asm volatile("cp.async.ca.shared.global [%0], [%1], 8;" :: "r"(dst), "l"(src));
    } else if (tid < 64) {                // qkdot: float per tt
        int tt = tid - 32;
        const float* src = xb_ + (size_t)tt * NUM_K;
        uint32_t dst = sbase + SC_XB + tt * 4;
        asm volatile("cp.async.ca.shared.global [%0], [%1], 4;" :: "r"(dst), "l"(src));
    }
}

__global__ __launch_bounds__(512) void gdn_scan(
    const float* __restrict__ qhat, const float* __restrict__ khat,
    const float* __restrict__ qkv, const float* __restrict__ egbeta,
    const float* __restrict__ qk, float* __restrict__ o)
{
    extern __shared__ __align__(128) char ssm[];
    const uint32_t sbase = smem_to_u32(ssm);
    const float* sf = (const float*)ssm;

    const int tid  = threadIdx.x;
    const int warp = tid >> 5;                  // 0..15
    const int lane = tid & 31;
    const int cg   = lane >> 3;                 // 0..3 column select within warp
    const int sl   = lane & 7;                  // sublane: dims [sl*16, sl*16+16)
    const int h    = blockIdx.x >> 1;           // 32 heads x 2 groups
    const int cb   = (blockIdx.x & 1) * 64;     // column base
    const int col  = cb + warp * 4 + cg;
    const int kh   = h >> 1;

    const float* kb_ = khat + kh * DK;
    const float* qb_ = qhat + kh * DK;
    const float* vb_ = qkv + 2 * KEY_DIM + h * DV + cb;
    const float* eb_ = egbeta + 2 * h;
    const float* xb_ = qk + kh;
    float*       op  = o + h * DV + col;

    const int NC = T_SEQ / SC_TC;                // 64

    float4 S0 = make_float4(0.f,0.f,0.f,0.f), S1 = make_float4(0.f,0.f,0.f,0.f);
    float4 S2 = make_float4(0.f,0.f,0.f,0.f), S3 = make_float4(0.f,0.f,0.f,0.f);

    scan_stage(sbase, kb_, qb_, vb_, eb_, xb_, tid);
    asm volatile("cp.async.commit_group;");

    for (int c = 0; c < NC; ++c) {
        if (c + 1 < NC) {
            size_t adv = (size_t)(c + 1) * SC_TC;
            scan_stage(sbase + ((c + 1) & 1) * SC_BUF,
                       kb_ + adv * KEY_DIM, qb_ + adv * KEY_DIM,
                       vb_ + adv * CONV_DIM, eb_ + adv * 2 * NUM_V,
                       xb_ + adv * NUM_K, tid);
            asm volatile("cp.async.commit_group;");
            asm volatile("cp.async.wait_group 1;");
        } else {
            asm volatile("cp.async.wait_group 0;");
        }
        __syncthreads();

        const int bo = (c & 1) * (SC_BUF / 4);
        const float* kbuf = sf + bo;
        const float* qbuf = sf + bo + SC_QB / 4;
        const float* vbuf = sf + bo + SC_VB / 4;
        const float* ebuf = sf + bo + SC_EB / 4;
        const float* xbuf = sf + bo + SC_XB / 4;

        // prefetch tt=0 of this chunk
        float4 kc[4], qc[4], kn[4], qn[4];
        {
            const float4* kr = (const float4*)(kbuf) + sl * 4;
            const float4* qr = (const float4*)(qbuf) + sl * 4;
#pragma unroll
            for (int j = 0; j < 4; ++j) { kc[j] = kr[j]; qc[j] = qr[j]; }
        }
        float vt = vbuf[cb ? (warp * 4 + cg) : (warp * 4 + cg)];
        vt = vbuf[warp * 4 + cg];
        float eg = ebuf[0], bt = ebuf[1], xq = xbuf[0];

        for (int tt = 0; tt < SC_TC; ++tt) {
            float vtn, egn, btn, xqn;
            if (tt + 1 < SC_TC) {
                const float4* kr = (const float4*)(kbuf + (tt + 1) * 128) + sl * 4;
                const float4* qr = (const float4*)(qbuf + (tt + 1) * 128) + sl * 4;
#pragma unroll
                for (int j = 0; j < 4; ++j) { kn[j] = kr[j]; qn[j] = qr[j]; }
                vtn = vbuf[(tt + 1) * 64 + warp * 4 + cg];
                egn = ebuf[(tt + 1) * 2];
                btn = ebuf[(tt + 1) * 2 + 1];
                xqn = xbuf[tt + 1];
            } else {
                vtn = vt; egn = eg; btn = bt; xqn = xq;
#pragma unroll
                for (int j = 0; j < 4; ++j) { kn[j] = kc[j]; qn[j] = qc[j]; }
            }

            float dk0 = kc[0].x*S0.x + kc[0].y*S0.y + kc[0].z*S0.z + kc[0].w*S0.w;
            float dk1 = kc[1].x*S1.x + kc[1].y*S1.y + kc[1].z*S1.z + kc[1].w*S1.w;
            float dk2 = kc[2].x*S2.x + kc[2].y*S2.y + kc[2].z*S2.z + kc[2].w*S2.w;
            float dk3 = kc[3].x*S3.x + kc[3].y*S3.y + kc[3].z*S3.z + kc[3].w*S3.w;
            float dq0 = qc[0].x*S0.x + qc[0].y*S0.y + qc[0].z*S0.z + qc[0].w*S0.w;
            float dq1 = qc[1].x*S1.x + qc[1].y*S1.y + qc[1].z*S1.z + qc[1].w*S1.w;
            float dq2 = qc[2].x*S2.x + qc[2].y*S2.y + qc[2].z*S2.z + qc[2].w*S2.w;
            float dq3 = qc[3].x*S3.x + qc[3].y*S3.y + qc[3].z*S3.z + qc[3].w*S3.w;
            float dk = (dk0 + dk1) + (dk2 + dk3);
            float dq = (dq0 + dq1) + (dq2 + dq3);
#pragma unroll
            for (int off = 4; off > 0; off >>= 1) {
                dk += __shfl_xor_sync(0xffffffffu, dk, off);
                dq += __shfl_xor_sync(0xffffffffu, dq, off);
            }
            const float delta = (vt - eg * dk) * bt;
            const float ot    = fmaf(eg, dq, xq * delta);
            S0.x = fmaf(S0.x, eg, kc[0].x * delta);
            S0.y = fmaf(S0.y, eg, kc[0].y * delta);
            S0.z = fmaf(S0.z, eg, kc[0].z * delta);
            S0.w = fmaf(S0.w, eg, kc[0].w * delta);
            S1.x = fmaf(S1.x, eg, kc[1].x * delta);
            S1.y = fmaf(S1.y, eg, kc[1].y * delta);
            S1.z = fmaf(S1.z, eg, kc[1].z * delta);
            S1.w = fmaf(S1.w, eg, kc[1].w * delta);
            S2.x = fmaf(S2.x, eg, kc[2].x * delta);
            S2.y = fmaf(S2.y, eg, kc[2].y * delta);
            S2.z = fmaf(S2.z, eg, kc[2].z * delta);
            S2.w = fmaf(S2.w, eg, kc[2].w * delta);
            S3.x = fmaf(S3.x, eg, kc[3].x * delta);
            S3.y = fmaf(S3.y, eg, kc[3].y * delta);
            S3.z = fmaf(S3.z, eg, kc[3].z * delta);
            S3.w = fmaf(S3.w, eg, kc[3].w * delta);
            if (sl == 0) op[(size_t)(c * SC_TC + tt) * VAL_DIM] = ot;
#pragma unroll
            for (int j = 0; j < 4; ++j) { kc[j] = kn[j]; qc[j] = qn[j]; }
            vt = vtn; eg = egn; bt = btn; xq = xqn;
        }
        __syncthreads();
    }
}

// ---------------- RMSNorm * norm_w * silu(z), write fp16 hi/lo directly ----------------
__global__ __launch_bounds__(256) void rms_gate_split(
    const float* __restrict__ o, const float* __restrict__ qkvz,
    const float* __restrict__ norm_w,
    __half* __restrict__ hi, __half* __restrict__ lo)
{
    int gid  = blockIdx.x * 8 + (threadIdx.x >> 5);
    int lane = threadIdx.x & 31;
    int t = gid >> 5;
    int h = gid & 31;
    const float* orow = o + (size_t)t * VAL_DIM + h * DV;
    float4 x = *(const float4*)(orow + lane * 4);
    float s = x.x * x.x + x.y * x.y + x.z * x.z + x.w * x.w;
#pragma unroll
    for (int off = 16; off > 0; off >>= 1) s += __shfl_xor_sync(0xffffffffu, s, off);
    float r = rsqrtf(s * (1.0f / DV) + 1e-6f);
    float4 z  = *(const float4*)(qkvz + (size_t)t * QKVZ_N + 2 * KEY_DIM + VAL_DIM + h * DV + lane * 4);
    float4 nw = *(const float4*)(norm_w + lane * 4);
    float4 y;
    y.x = x.x * r * nw.x * siluf_(z.x);
    y.y = x.y * r * nw.y * siluf_(z.y);
    y.z = x.z * r * nw.z * siluf_(z.z);
    y.w = x.w * r * nw.w * siluf_(z.w);
    __half h0 = __float2half_rn(y.x), h1 = __float2half_rn(y.y);
    __half h2 = __float2half_rn(y.z), h3 = __float2half_rn(y.w);
    __half l0 = __float2half_rn(y.x - __half2float(h0));
    __half l1 = __float2half_rn(y.y - __half2float(h1));
    __half l2 = __float2half_rn(y.z - __half2float(h2));
    __half l3 = __float2half_rn(y.w - __half2float(h3));
    union { __half2 h2v[2]; uint2 u; } H, L;
    H.h2v[0] = __halves2half2(h0, h1); H.h2v[1] = __halves2half2(h2, h3);
    L.h2v[0] = __halves2half2(l0, l1); L.h2v[1] = __halves2half2(l2, l3);
    int i4 = (t * VAL_DIM + h * DV) / 4 + lane;
    ((uint2*)hi)[i4] = H.u;
    ((uint2*)lo)[i4] = L.u;
}

// ---------------- launch ----------------
extern "C" void kernel_launch(void* const* d_in, const int* in_sizes, int n_in,
                              void* d_out, int out_size)
{
    const float* h_in    = (const float*)d_in[0];
    const float* W_qkvz  = (const float*)d_in[1];
    const float* W_ba    = (const float*)d_in[2];
    const float* conv_w  = (const float*)d_in[3];
    const float* dt_bias = (const float*)d_in[4];
    const float* A_log   = (const float*)d_in[5];
    const float* norm_w  = (const float*)d_in[6];
    const float* W_out   = (const float*)d_in[7];
    float* out = (float*)d_out;

    float *qkvz, *qkv, *ba, *qhat, *khat, *qkdot, *oscan;
    float2* egbeta;
    __half *Wq, *Wo, *A_hi, *A_lo;
    cudaGetSymbolAddress((void**)&qkvz,   g_qkvz);
    cudaGetSymbolAddress((void**)&qkv,    g_qkv);
    cudaGetSymbolAddress((void**)&ba,     g_ba);
    cudaGetSymbolAddress((void**)&egbeta, g_egbeta);
    cudaGetSymbolAddress((void**)&qhat,   g_qhat);
    cudaGetSymbolAddress((void**)&khat,   g_khat);
    cudaGetSymbolAddress((void**)&qkdot,  g_qkdot);
    cudaGetSymbolAddress((void**)&oscan,  g_oscan);
    cudaGetSymbolAddress((void**)&Wq,     g_Wq);
    cudaGetSymbolAddress((void**)&Wo,     g_Wo);
    cudaGetSymbolAddress((void**)&A_hi,   g_A_hi);
    cudaGetSymbolAddress((void**)&A_lo,   g_A_lo);

    cudaFuncSetAttribute(gemm_tc<1>, cudaFuncAttributeMaxDynamicSharedMemorySize, GT_SMEM);
    cudaFuncSetAttribute(gemm_tc<0>, cudaFuncAttributeMaxDynamicSharedMemorySize, GT_SMEM);
    cudaFuncSetAttribute(gdn_scan, cudaFuncAttributeMaxDynamicSharedMemorySize, SC_SMEM);

    // prep
    {
        dim3 blk(32, 8);
        tr_half<<<dim3(QKVZ_N / 32, HID / 32), blk>>>(W_qkvz, Wq, HID, QKVZ_N);
        tr_half<<<dim3(HID / 32, VAL_DIM / 32), blk>>>(W_out, Wo, VAL_DIM, HID);
    }
    cvt_split<<<(T_SEQ * HID / 4 + 255) / 256, 256>>>(h_in, A_hi, A_lo, T_SEQ * HID / 4);

    // GEMM1: qkvz = h @ W_qkvz   [2048 x 12288], K=2048 (split-A, 2 passes)
    gemm_tc<1><<<dim3(T_SEQ / 128, QKVZ_N / 128), 256, GT_SMEM>>>(A_hi, A_lo, Wq, qkvz, QKVZ_N, HID);

    gemm_ba<<<T_SEQ / 64, 256>>>(h_in, W_ba, ba);
    conv_silu<<<((T_SEQ / 4) * CONV_DIM) / 256, 256>>>(qkvz, conv_w, qkv);
    gate_prep<<<(T_SEQ * NUM_V) / 256, 256>>>(ba, A_log, dt_bias, egbeta);
    l2norm_qk_dot<<<(T_SEQ * NUM_K) / 8, 256>>>(qkv, qhat, khat, qkdot);
    gdn_scan<<<NUM_V * 2, 512, SC_SMEM>>>(qhat, khat, qkv, (const float*)egbeta, qkdot, oscan);
    rms_gate_split<<<(T_SEQ * NUM_V) / 8, 256>>>(oscan, qkvz, norm_w, A_hi, A_lo);

    // GEMM2: out = gated @ W_out  [2048 x 2048], K=4096 (single-pass fp16 A)
    gemm_tc<0><<<dim3(T_SEQ / 128, HID / 128), 256, GT_SMEM>>>(A_hi, A_lo, Wo, out, HID, VAL_DIM);
}

// round 15
// speedup vs baseline: 2.2665x; 2.2665x over previous
#include <cuda_runtime.h>
#include <cuda_fp16.h>
#include <math.h>
#include <stdint.h>

// ---------------- problem constants ----------------
#define T_SEQ   2048
#define HID     2048
#define NUM_K   16
#define NUM_V   32
#define DK      128
#define DV      128
#define KEY_DIM 2048
#define VAL_DIM 4096
#define CONV_DIM 8192
#define QKVZ_N  12288
#define QSCALE  0.08838834764831845f

// ---------------- scratch ----------------
__device__ float  g_qkvz  [T_SEQ * QKVZ_N];
__device__ float  g_qkv   [T_SEQ * CONV_DIM];
__device__ float  g_ba    [T_SEQ * 64];
__device__ float2 g_egbeta[T_SEQ * NUM_V];
__device__ float  g_qhat  [T_SEQ * KEY_DIM];
__device__ float  g_khat  [T_SEQ * KEY_DIM];
__device__ float  g_qkdot [T_SEQ * NUM_K];
__device__ float  g_oscan [T_SEQ * VAL_DIM];

// fp16 operands: weights single fp16 (W^T), activations split hi/lo
__device__ __half g_Wq[QKVZ_N * HID];
__device__ __half g_Wo[HID * VAL_DIM];
__device__ __half g_A_hi[T_SEQ * VAL_DIM];
__device__ __half g_A_lo[T_SEQ * VAL_DIM];

// ---------------- helpers ----------------
__device__ __forceinline__ float sigmoidf_(float x) { return 1.0f / (1.0f + __expf(-x)); }
__device__ __forceinline__ float siluf_(float x)    { return x * sigmoidf_(x); }

__device__ __forceinline__ uint32_t smem_to_u32(const void* p) {
    uint32_t a;
    asm("{ .reg .u64 t; cvta.to.shared.u64 t, %1; cvt.u32.u64 %0, t; }" : "=r"(a) : "l"(p));
    return a;
}
__device__ __forceinline__ void ldsm4(uint32_t& r0, uint32_t& r1, uint32_t& r2, uint32_t& r3,
                                      uint32_t addr) {
    asm volatile("ldmatrix.sync.aligned.m8n8.x4.shared.b16 {%0,%1,%2,%3}, [%4];"
                 : "=r"(r0), "=r"(r1), "=r"(r2), "=r"(r3) : "r"(addr));
}
__device__ __forceinline__ void mma16816(float* d, const uint32_t* a, const uint32_t* b) {
    asm volatile("mma.sync.aligned.m16n8k16.row.col.f32.f16.f16.f32 "
                 "{%0,%1,%2,%3}, {%4,%5,%6,%7}, {%8,%9}, {%0,%1,%2,%3};"
                 : "+f"(d[0]), "+f"(d[1]), "+f"(d[2]), "+f"(d[3])
                 : "r"(a[0]), "r"(a[1]), "r"(a[2]), "r"(a[3]), "r"(b[0]), "r"(b[1]));
}

// ---------------- prep: fp32 -> fp16 hi/lo split ----------------
__global__ __launch_bounds__(256) void cvt_split(
    const float* __restrict__ x, __half* __restrict__ hi,
    __half* __restrict__ lo, int n4)
{
    int i = blockIdx.x * 256 + threadIdx.x;
    if (i >= n4) return;
    float4 v = ((const float4*)x)[i];
    __half h0 = __float2half_rn(v.x), h1 = __float2half_rn(v.y);
    __half h2 = __float2half_rn(v.z), h3 = __float2half_rn(v.w);
    __half l0 = __float2half_rn(v.x - __half2float(h0));
    __half l1 = __float2half_rn(v.y - __half2float(h1));
    __half l2 = __float2half_rn(v.z - __half2float(h2));
    __half l3 = __float2half_rn(v.w - __half2float(h3));
    union { __half2 h2v[2]; uint2 u; } H, L;
    H.h2v[0] = __halves2half2(h0, h1); H.h2v[1] = __halves2half2(h2, h3);
    L.h2v[0] = __halves2half2(l0, l1); L.h2v[1] = __halves2half2(l2, l3);
    ((uint2*)hi)[i] = H.u;
    ((uint2*)lo)[i] = L.u;
}

// ---------------- prep: W [K][N] fp32 -> W^T [N][K] fp16 ----------------
__global__ __launch_bounds__(256) void tr_half(
    const float* __restrict__ W, __half* __restrict__ out, int K, int N)
{
    __shared__ float t[32][33];
    int n0 = blockIdx.x * 32, k0 = blockIdx.y * 32;
    int tx = threadIdx.x, ty = threadIdx.y;
#pragma unroll
    for (int j = 0; j < 4; ++j)
        t[ty + j * 8][tx] = W[(size_t)(k0 + ty + j * 8) * N + n0 + tx];
    __syncthreads();
#pragma unroll
    for (int j = 0; j < 4; ++j) {
        int n = ty + j * 8;
        out[(size_t)(n0 + n) * K + k0 + tx] = __float2half_rn(t[tx][n]);
    }
}

// ---------------- mma.sync GEMM: 128x128 CTA, 256 threads, BK=64, 2-stage, 2 CTA/SM ----------------
#define SSTR   144
#define SZ_A   (128 * SSTR)
#define SZ_B   (128 * SSTR)
#define BUF_SZ (2 * SZ_A + SZ_B)
#define GT_SMEM (2 * BUF_SZ)

template<int ITERS>
__device__ __forceinline__ void cpa_stage(uint32_t sdst, const char* g, int Kb, int tid) {
#pragma unroll
    for (int i = 0; i < ITERS; ++i) {
        int idx = tid + i * 256;
        int row = idx >> 3;
        int q   = (idx & 7) << 4;
        uint32_t d = sdst + row * SSTR + q;
        const char* s = g + (size_t)row * Kb + q;
        asm volatile("cp.async.cg.shared.global [%0], [%1], 16;" :: "r"(d), "l"(s));
    }
}

template<int USE_LO>
__global__ __launch_bounds__(256, 2) void gemm_tc(
    const __half* __restrict__ Ahi, const __half* __restrict__ Alo,
    const __half* __restrict__ B, float* __restrict__ C, int N, int K)
{
    extern __shared__ __align__(128) char smem[];
    const uint32_t sb = smem_to_u32(smem);

    const int tid  = threadIdx.x;
    const int wid  = tid >> 5;
    const int lane = tid & 31;
    const int bm   = blockIdx.x * 128;
    const int bn   = blockIdx.y * 128;
    const int wm   = (wid >> 1) * 32;
    const int wn   = (wid & 1) * 64;
    const int Kb   = K * 2;

    const char* gAh = (const char*)(Ahi + (size_t)bm * K);
    const char* gAl = (const char*)(Alo + (size_t)bm * K);
    const char* gB  = (const char*)(B   + (size_t)bn * K);

    float acc[2][8][4];
#pragma unroll
    for (int i = 0; i < 2; ++i)
#pragma unroll
        for (int j = 0; j < 8; ++j)
#pragma unroll
            for (int r = 0; r < 4; ++r) acc[i][j][r] = 0.0f;

    const uint32_t aoff = (lane & 15) * SSTR + ((lane >> 4) << 4);
    const uint32_t boff = ((lane & 7) + ((lane >> 4) << 3)) * SSTR + (((lane >> 3) & 1) << 4);

    const int nk = K >> 6;

    {
        uint32_t sbuf = sb;
        cpa_stage<4>(sbuf,            gAh, Kb, tid);
        if (USE_LO) cpa_stage<4>(sbuf + SZ_A, gAl, Kb, tid);
        cpa_stage<4>(sbuf + 2 * SZ_A, gB,  Kb, tid);
        asm volatile("cp.async.commit_group;");
    }

    for (int kt = 0; kt < nk; ++kt) {
        asm volatile("cp.async.wait_group 0;");
        __syncthreads();

        if (kt + 1 < nk) {
            uint32_t sbuf = sb + ((kt + 1) & 1) * BUF_SZ;
            size_t ko = (size_t)(kt + 1) * 128;
            cpa_stage<4>(sbuf,            gAh + ko, Kb, tid);
            if (USE_LO) cpa_stage<4>(sbuf + SZ_A, gAl + ko, Kb, tid);
            cpa_stage<4>(sbuf + 2 * SZ_A, gB  + ko, Kb, tid);
            asm volatile("cp.async.commit_group;");
        }

        const uint32_t sAh = sb + (kt & 1) * BUF_SZ;
        const uint32_t sAl = sAh + SZ_A;
        const uint32_t sB  = sAh + 2 * SZ_A;

#pragma unroll
        for (int ks = 0; ks < 4; ++ks) {
            const uint32_t kb = ks * 32;
            uint32_t ah[2][4], al[2][4];
#pragma unroll
            for (int mt = 0; mt < 2; ++mt) {
                uint32_t base = (wm + mt * 16) * SSTR + aoff + kb;
                ldsm4(ah[mt][0], ah[mt][1], ah[mt][2], ah[mt][3], sAh + base);
                if (USE_LO)
                    ldsm4(al[mt][0], al[mt][1], al[mt][2], al[mt][3], sAl + base);
            }
#pragma unroll
            for (int pr = 0; pr < 4; ++pr) {
                uint32_t bbase = (wn + pr * 16) * SSTR + boff + kb;
                uint32_t h0, h1, h2, h3;
                ldsm4(h0, h1, h2, h3, sB + bbase);
                uint32_t b0[2] = {h0, h1}, b1[2] = {h2, h3};
#pragma unroll
                for (int mt = 0; mt < 2; ++mt) {
                    mma16816(acc[mt][2 * pr],     ah[mt], b0);
                    mma16816(acc[mt][2 * pr + 1], ah[mt], b1);
                    if (USE_LO) {
                        mma16816(acc[mt][2 * pr],     al[mt], b0);
                        mma16816(acc[mt][2 * pr + 1], al[mt], b1);
                    }
                }
            }
        }
    }

    const int g  = lane >> 2;
    const int tg = lane & 3;
#pragma unroll
    for (int mt = 0; mt < 2; ++mt) {
#pragma unroll
        for (int nt = 0; nt < 8; ++nt) {
            const float* d = acc[mt][nt];
            size_t r = (size_t)(bm + wm + mt * 16 + g) * N + bn + wn + nt * 8 + tg * 2;
            *(float2*)&C[r] = make_float2(d[0], d[1]);
            *(float2*)&C[r + 8 * (size_t)N] = make_float2(d[2], d[3]);
        }
    }
}

// ---------------- tiled small GEMM: ba = h @ W_ba (2048x64, K=2048) ----------------
__global__ __launch_bounds__(256) void gemm_ba(
    const float* __restrict__ A, const float* __restrict__ B, float* __restrict__ C)
{
    __shared__ float sh[64][65];
    __shared__ float sB[64][65];
    const int tid = threadIdx.x;
    const int col = tid & 63;
    const int rg  = tid >> 6;
    const int br  = blockIdx.x * 64;

    float acc[16];
#pragma unroll
    for (int r = 0; r < 16; ++r) acc[r] = 0.0f;

    for (int kt = 0; kt < HID / 64; ++kt) {
#pragma unroll
        for (int i = 0; i < 16; ++i) {
            int idx = tid + i * 256;
            int row = idx >> 6, kk = idx & 63;
            sh[row][kk] = A[(size_t)(br + row) * HID + kt * 64 + kk];
            sB[row][kk] = B[(size_t)(kt * 64 + row) * 64 + kk];
        }
        __syncthreads();
#pragma unroll 16
        for (int kk = 0; kk < 64; ++kk) {
            float b = sB[kk][col];
#pragma unroll
            for (int r = 0; r < 16; ++r)
                acc[r] = fmaf(sh[rg * 16 + r][kk], b, acc[r]);
        }
        __syncthreads();
    }
#pragma unroll
    for (int r = 0; r < 16; ++r)
        C[(size_t)(br + rg * 16 + r) * 64 + col] = acc[r];
}

// ---------------- causal depthwise conv (K=4) + SiLU, 4 t per thread ----------------
__global__ __launch_bounds__(256) void conv_silu(
    const float* __restrict__ qkvz, const float* __restrict__ conv_w,
    float* __restrict__ out)
{
    int idx = blockIdx.x * blockDim.x + threadIdx.x;
    if (idx >= (T_SEQ / 4) * CONV_DIM) return;
    int tq = idx >> 13;
    int c  = idx & (CONV_DIM - 1);
    int t0 = tq * 4;
    const float* w = conv_w + c * 4;
    float xv[7];
#pragma unroll
    for (int j = 0; j < 7; ++j) {
        int tt = t0 - 3 + j;
        xv[j] = (tt >= 0) ? qkvz[(size_t)tt * QKVZ_N + c] : 0.0f;
    }
#pragma unroll
    for (int i = 0; i < 4; ++i) {
        float a = w[0] * xv[i];
        a = fmaf(w[1], xv[i + 1], a);
        a = fmaf(w[2], xv[i + 2], a);
        a = fmaf(w[3], xv[i + 3], a);
        out[(size_t)(t0 + i) * CONV_DIM + c] = siluf_(a);
    }
}

// ---------------- gating ----------------
__global__ __launch_bounds__(256) void gate_prep(
    const float* __restrict__ ba, const float* __restrict__ A_log,
    const float* __restrict__ dt_bias, float2* __restrict__ egbeta)
{
    int i = blockIdx.x * blockDim.x + threadIdx.x;
    if (i >= T_SEQ * NUM_V) return;
    int t = i >> 5;
    int h = i & 31;
    float b = ba[(size_t)t * 64 + h];
    float a = ba[(size_t)t * 64 + 32 + h];
    float x = a + dt_bias[h];
    float sp = (x > 20.0f) ? x : log1pf(expf(x));
    float g = -expf(A_log[h]) * sp;
    egbeta[i] = make_float2(expf(g), sigmoidf_(b));
}

// ---------------- fused l2norm(q,k) + qk dot: one warp per (t, key-head) ----------------
__global__ __launch_bounds__(256) void l2norm_qk_dot(
    const float* __restrict__ qkv, float* __restrict__ qhat,
    float* __restrict__ khat, float* __restrict__ qkdot)
{
    int gid  = blockIdx.x * 8 + (threadIdx.x >> 5);
    int lane = threadIdx.x & 31;
    int t  = gid >> 4;
    int kh = gid & 15;
    const float* qsrc = qkv + (size_t)t * CONV_DIM + kh * DK;
    float4 q = *((const float4*)qsrc + lane);
    float4 k = *((const float4*)(qsrc + KEY_DIM) + lane);
    float sq  = q.x * q.x + q.y * q.y + q.z * q.z + q.w * q.w;
    float sk  = k.x * k.x + k.y * k.y + k.z * k.z + k.w * k.w;
    float sqk = q.x * k.x + q.y * k.y + q.z * k.z + q.w * k.w;
#pragma unroll
    for (int off = 16; off > 0; off >>= 1) {
        sq  += __shfl_xor_sync(0xffffffffu, sq,  off);
        sk  += __shfl_xor_sync(0xffffffffu, sk,  off);
        sqk += __shfl_xor_sync(0xffffffffu, sqk, off);
    }
    float rq = rsqrtf(sq + 1e-6f) * QSCALE;
    float rk = rsqrtf(sk + 1e-6f);
    size_t base = (size_t)t * KEY_DIM + kh * DK;
    *((float4*)(qhat + base) + lane) = make_float4(q.x * rq, q.y * rq, q.z * rq, q.w * rq);
    *((float4*)(khat + base) + lane) = make_float4(k.x * rk, k.y * rk, k.z * rk, k.w * rk);
    if (lane == 0) qkdot[t * NUM_K + kh] = sqk * rq * rk;
}

// ---------------- gated delta scan: smem-staged, double-buffered, 16 warps/CTA ----------------
// CTA = (head, 32-col group); 16 warps x 2 cols; chunks of 32 timesteps via cp.async.
// smem per buffer (bytes): K 16384 | Q 16384 | V 4096 | EB 256 | XQ 128 -> pad 37376
// plus a 4 KB output-staging tile (32 tt x 32 cols) after the two buffers.
#define SC_TC   32
#define SC_QB   16384
#define SC_VB   32768
#define SC_EB   36864
#define SC_XB   37120
#define SC_BUF  37376
#define SC_SMEM (2 * SC_BUF + 4096)

__device__ __forceinline__ void scan_stage(
    uint32_t sbase, const float* kb_, const float* qb_,
    const float* vb_, const float* eb_, const float* xb_, int tid)
{
    // k/q: j = 0..31 float4s per row; store even j at [0,256)B, odd j at [256,512)B
#pragma unroll
    for (int i = 0; i < 4; ++i) {
        int idx = tid + i * 512;          // 0..2047
        int isq = idx >> 10;
        int r   = idx & 1023;
        int tt  = r >> 5;
        int j   = r & 31;
        const float* src = (isq ? qb_ : kb_) + (size_t)tt * KEY_DIM + j * 4;
        uint32_t dst = sbase + (isq ? SC_QB : 0) + tt * 512 + ((j & 1) << 8) + ((j >> 1) << 4);
        asm volatile("cp.async.ca.shared.global [%0], [%1], 16;" :: "r"(dst), "l"(src));
    }
    if (tid < 256) {                      // v: 32 floats per tt = 8 float4
        int tt = tid >> 3, j = tid & 7;
        const float* src = vb_ + (size_t)tt * CONV_DIM + j * 4;
        uint32_t dst = sbase + SC_VB + tt * 128 + j * 16;
        asm volatile("cp.async.ca.shared.global [%0], [%1], 16;" :: "r"(dst), "l"(src));
    } else if (tid < 288) {               // egbeta: float2 per tt
        int tt = tid - 256;
        const float* src = eb_ + (size_t)tt * (2 * NUM_V);
        uint32_t dst = sbase + SC_EB + tt * 8;
        asm volatile("cp.async.ca.shared.global [%0], [%1], 8;" :: "r"(dst), "l"(src));
    } else if (tid < 320) {               // qkdot: float per tt
        int tt = tid - 288;
        const float* src = xb_ + (size_t)tt * NUM_K;
        uint32_t dst = sbase + SC_XB + tt * 4;
        asm volatile("cp.async.ca.shared.global [%0], [%1], 4;" :: "r"(dst), "l"(src));
    }
}

__global__ __launch_bounds__(512) void gdn_scan(
    const float* __restrict__ qhat, const float* __restrict__ khat,
    const float* __restrict__ qkv, const float* __restrict__ egbeta,
    const float* __restrict__ qk, float* __restrict__ o)
{
    extern __shared__ __align__(128) char ssm[];
    const uint32_t sbase = smem_to_u32(ssm);
    const float* sf = (const float*)ssm;
    float* souts = (float*)(ssm + 2 * SC_BUF);

    const int tid  = threadIdx.x;
    const int warp = tid >> 5;                  // 0..15
    const int lane = tid & 31;
    const int half = lane >> 4;
    const int sl   = lane & 15;
    const int h    = blockIdx.x >> 2;           // 32 heads x 4 groups
    const int cb   = (blockIdx.x & 3) * 32;     // column base
    const int kh   = h >> 1;

    const float* kb_ = khat + kh * DK;
    const float* qb_ = qhat + kh * DK;
    const float* vb_ = qkv + 2 * KEY_DIM + h * DV + cb;
    const float* eb_ = egbeta + 2 * h;
    const float* xb_ = qk + kh;
    float*       ob  = o + h * DV + cb;

    const int NC = T_SEQ / SC_TC;                // 64

    float4 Sa = make_float4(0.f, 0.f, 0.f, 0.f);
    float4 Sb = make_float4(0.f, 0.f, 0.f, 0.f);

    scan_stage(sbase, kb_, qb_, vb_, eb_, xb_, tid);
    asm volatile("cp.async.commit_group;");

    for (int c = 0; c < NC; ++c) {
        if (c + 1 < NC) {
            size_t adv = (size_t)(c + 1) * SC_TC;
            scan_stage(sbase + ((c + 1) & 1) * SC_BUF,
                       kb_ + adv * KEY_DIM, qb_ + adv * KEY_DIM,
                       vb_ + adv * CONV_DIM, eb_ + adv * 2 * NUM_V,
                       xb_ + adv * NUM_K, tid);
            asm volatile("cp.async.commit_group;");
            asm volatile("cp.async.wait_group 1;");
        } else {
            asm volatile("cp.async.wait_group 0;");
        }
        __syncthreads();

        const int bo = (c & 1) * (SC_BUF / 4);
        for (int tt = 0; tt < SC_TC; ++tt) {
            const float* kr = sf + bo + tt * 128;
            const float* qr = sf + bo + SC_QB / 4 + tt * 128;
            float4 k0 = *(const float4*)(kr + sl * 4);
            float4 k1 = *(const float4*)(kr + 64 + sl * 4);
            float4 q0 = *(const float4*)(qr + sl * 4);
            float4 q1 = *(const float4*)(qr + 64 + sl * 4);
            float  vt = sf[bo + SC_VB / 4 + tt * 32 + warp * 2 + half];
            float  eg = sf[bo + SC_EB / 4 + tt * 2];
            float  bt = sf[bo + SC_EB / 4 + tt * 2 + 1];
            float  xq = sf[bo + SC_XB / 4 + tt];

            float dk = k0.x * Sa.x + k0.y * Sa.y + k0.z * Sa.z + k0.w * Sa.w
                     + k1.x * Sb.x + k1.y * Sb.y + k1.z * Sb.z + k1.w * Sb.w;
            float dq = q0.x * Sa.x + q0.y * Sa.y + q0.z * Sa.z + q0.w * Sa.w
                     + q1.x * Sb.x + q1.y * Sb.y + q1.z * Sb.z + q1.w * Sb.w;
#pragma unroll
            for (int off = 8; off > 0; off >>= 1) {
                dk += __shfl_xor_sync(0xffffffffu, dk, off);
                dq += __shfl_xor_sync(0xffffffffu, dq, off);
            }
            const float delta = (vt - eg * dk) * bt;
            const float ot    = fmaf(eg, dq, xq * delta);
            Sa.x = fmaf(Sa.x, eg, k0.x * delta);
            Sa.y = fmaf(Sa.y, eg, k0.y * delta);
            Sa.z = fmaf(Sa.z, eg, k0.z * delta);
            Sa.w = fmaf(Sa.w, eg, k0.w * delta);
            Sb.x = fmaf(Sb.x, eg, k1.x * delta);
            Sb.y = fmaf(Sb.y, eg, k1.y * delta);
            Sb.z = fmaf(Sb.z, eg, k1.z * delta);
            Sb.w = fmaf(Sb.w, eg, k1.w * delta);
            if (sl == 0) souts[tt * 32 + warp * 2 + half] = ot;
        }
        __syncthreads();

        // cooperative coalesced writeback of the 32x32 output tile
        {
            int tt = tid >> 4;
            int j  = (tid & 15) * 2;
            float2 v2 = *(float2*)&souts[tt * 32 + j];
            *(float2*)&ob[(size_t)(c * SC_TC + tt) * VAL_DIM + j] = v2;
        }
        // next iteration's top-of-loop __syncthreads orders souts reuse
    }
}

// ---------------- RMSNorm * norm_w * silu(z), write fp16 hi/lo directly ----------------
__global__ __launch_bounds__(256) void rms_gate_split(
    const float* __restrict__ o, const float* __restrict__ qkvz,
    const float* __restrict__ norm_w,
    __half* __restrict__ hi, __half* __restrict__ lo)
{
    int gid  = blockIdx.x * 8 + (threadIdx.x >> 5);
    int lane = threadIdx.x & 31;
    int t = gid >> 5;
    int h = gid & 31;
    const float* orow = o + (size_t)t * VAL_DIM + h * DV;
    float4 x = *(const float4*)(orow + lane * 4);
    float s = x.x * x.x + x.y * x.y + x.z * x.z + x.w * x.w;
#pragma unroll
    for (int off = 16; off > 0; off >>= 1) s += __shfl_xor_sync(0xffffffffu, s, off);
    float r = rsqrtf(s * (1.0f / DV) + 1e-6f);
    float4 z  = *(const float4*)(qkvz + (size_t)t * QKVZ_N + 2 * KEY_DIM + VAL_DIM + h * DV + lane * 4);
    float4 nw = *(const float4*)(norm_w + lane * 4);
    float4 y;
    y.x = x.x * r * nw.x * siluf_(z.x);
    y.y = x.y * r * nw.y * siluf_(z.y);
    y.z = x.z * r * nw.z * siluf_(z.z);
    y.w = x.w * r * nw.w * siluf_(z.w);
    __half h0 = __float2half_rn(y.x), h1 = __float2half_rn(y.y);
    __half h2 = __float2half_rn(y.z), h3 = __float2half_rn(y.w);
    __half l0 = __float2half_rn(y.x - __half2float(h0));
    __half l1 = __float2half_rn(y.y - __half2float(h1));
    __half l2 = __float2half_rn(y.z - __half2float(h2));
    __half l3 = __float2half_rn(y.w - __half2float(h3));
    union { __half2 h2v[2]; uint2 u; } H, L;
    H.h2v[0] = __halves2half2(h0, h1); H.h2v[1] = __halves2half2(h2, h3);
    L.h2v[0] = __halves2half2(l0, l1); L.h2v[1] = __halves2half2(l2, l3);
    int i4 = (t * VAL_DIM + h * DV) / 4 + lane;
    ((uint2*)hi)[i4] = H.u;
    ((uint2*)lo)[i4] = L.u;
}

// ---------------- launch ----------------
extern "C" void kernel_launch(void* const* d_in, const int* in_sizes, int n_in,
                              void* d_out, int out_size)
{
    const float* h_in    = (const float*)d_in[0];
    const float* W_qkvz  = (const float*)d_in[1];
    const float* W_ba    = (const float*)d_in[2];
    const float* conv_w  = (const float*)d_in[3];
    const float* dt_bias = (const float*)d_in[4];
    const float* A_log   = (const float*)d_in[5];
    const float* norm_w  = (const float*)d_in[6];
    const float* W_out   = (const float*)d_in[7];
    float* out = (float*)d_out;

    float *qkvz, *qkv, *ba, *qhat, *khat, *qkdot, *oscan;
    float2* egbeta;
    __half *Wq, *Wo, *A_hi, *A_lo;
    cudaGetSymbolAddress((void**)&qkvz,   g_qkvz);
    cudaGetSymbolAddress((void**)&qkv,    g_qkv);
    cudaGetSymbolAddress((void**)&ba,     g_ba);
    cudaGetSymbolAddress((void**)&egbeta, g_egbeta);
    cudaGetSymbolAddress((void**)&qhat,   g_qhat);
    cudaGetSymbolAddress((void**)&khat,   g_khat);
    cudaGetSymbolAddress((void**)&qkdot,  g_qkdot);
    cudaGetSymbolAddress((void**)&oscan,  g_oscan);
    cudaGetSymbolAddress((void**)&Wq,     g_Wq);
    cudaGetSymbolAddress((void**)&Wo,     g_Wo);
    cudaGetSymbolAddress((void**)&A_hi,   g_A_hi);
    cudaGetSymbolAddress((void**)&A_lo,   g_A_lo);

    cudaFuncSetAttribute(gemm_tc<1>, cudaFuncAttributeMaxDynamicSharedMemorySize, GT_SMEM);
    cudaFuncSetAttribute(gemm_tc<0>, cudaFuncAttributeMaxDynamicSharedMemorySize, GT_SMEM);
    cudaFuncSetAttribute(gdn_scan, cudaFuncAttributeMaxDynamicSharedMemorySize, SC_SMEM);

    // prep
    {
        dim3 blk(32, 8);
        tr_half<<<dim3(QKVZ_N / 32, HID / 32), blk>>>(W_qkvz, Wq, HID, QKVZ_N);
        tr_half<<<dim3(HID / 32, VAL_DIM / 32), blk>>>(W_out, Wo, VAL_DIM, HID);
    }
    cvt_split<<<(T_SEQ * HID / 4 + 255) / 256, 256>>>(h_in, A_hi, A_lo, T_SEQ * HID / 4);

    // GEMM1: qkvz = h @ W_qkvz   [2048 x 12288], K=2048 (split-A, 2 passes)
    gemm_tc<1><<<dim3(T_SEQ / 128, QKVZ_N / 128), 256, GT_SMEM>>>(A_hi, A_lo, Wq, qkvz, QKVZ_N, HID);

    gemm_ba<<<T_SEQ / 64, 256>>>(h_in, W_ba, ba);
    conv_silu<<<((T_SEQ / 4) * CONV_DIM) / 256, 256>>>(qkvz, conv_w, qkv);
    gate_prep<<<(T_SEQ * NUM_V) / 256, 256>>>(ba, A_log, dt_bias, egbeta);
    l2norm_qk_dot<<<(T_SEQ * NUM_K) / 8, 256>>>(qkv, qhat, khat, qkdot);
    gdn_scan<<<NUM_V * 4, 512, SC_SMEM>>>(qhat, khat, qkv, (const float*)egbeta, qkdot, oscan);
    rms_gate_split<<<(T_SEQ * NUM_V) / 8, 256>>>(oscan, qkvz, norm_w, A_hi, A_lo);

    // GEMM2: out = gated @ W_out  [2048 x 2048], K=4096 (single-pass fp16 A)
    gemm_tc<0><<<dim3(T_SEQ / 128, HID / 128), 256, GT_SMEM>>>(A_hi, A_lo, Wo, out, HID, VAL_DIM);
}

// round 16
// speedup vs baseline: 2.5169x; 1.1105x over previous
#include <cuda_runtime.h>
#include <cuda_fp16.h>
#include <math.h>
#include <stdint.h>

// ---------------- problem constants ----------------
#define T_SEQ   2048
#define HID     2048
#define NUM_K   16
#define NUM_V   32
#define DK      128
#define DV      128
#define KEY_DIM 2048
#define VAL_DIM 4096
#define CONV_DIM 8192
#define QKVZ_N  12288
#define QSCALE  0.08838834764831845f

// ---------------- scratch ----------------
__device__ float  g_qkvz  [T_SEQ * QKVZ_N];
__device__ float  g_qkv   [T_SEQ * CONV_DIM];
__device__ float  g_ba    [T_SEQ * 64];
__device__ float2 g_egbeta[T_SEQ * NUM_V];
__device__ float  g_qhat  [T_SEQ * KEY_DIM];
__device__ float  g_khat  [T_SEQ * KEY_DIM];
__device__ float  g_qkdot [T_SEQ * NUM_K];
__device__ float  g_oscan [T_SEQ * VAL_DIM];

// fp16 operands: weights single fp16 (W^T), activations split hi/lo
__device__ __half g_Wq[QKVZ_N * HID];
__device__ __half g_Wo[HID * VAL_DIM];
__device__ __half g_A_hi[T_SEQ * VAL_DIM];
__device__ __half g_A_lo[T_SEQ * VAL_DIM];

// ---------------- helpers ----------------
__device__ __forceinline__ float sigmoidf_(float x) { return 1.0f / (1.0f + __expf(-x)); }
__device__ __forceinline__ float siluf_(float x)    { return x * sigmoidf_(x); }

__device__ __forceinline__ uint32_t smem_to_u32(const void* p) {
    uint32_t a;
    asm("{ .reg .u64 t; cvta.to.shared.u64 t, %1; cvt.u32.u64 %0, t; }" : "=r"(a) : "l"(p));
    return a;
}
__device__ __forceinline__ void ldsm4(uint32_t& r0, uint32_t& r1, uint32_t& r2, uint32_t& r3,
                                      uint32_t addr) {
    asm volatile("ldmatrix.sync.aligned.m8n8.x4.shared.b16 {%0,%1,%2,%3}, [%4];"
                 : "=r"(r0), "=r"(r1), "=r"(r2), "=r"(r3) : "r"(addr));
}
__device__ __forceinline__ void mma16816(float* d, const uint32_t* a, const uint32_t* b) {
    asm volatile("mma.sync.aligned.m16n8k16.row.col.f32.f16.f16.f32 "
                 "{%0,%1,%2,%3}, {%4,%5,%6,%7}, {%8,%9}, {%0,%1,%2,%3};"
                 : "+f"(d[0]), "+f"(d[1]), "+f"(d[2]), "+f"(d[3])
                 : "r"(a[0]), "r"(a[1]), "r"(a[2]), "r"(a[3]), "r"(b[0]), "r"(b[1]));
}

// ---------------- prep: fp32 -> fp16 hi/lo split ----------------
__global__ __launch_bounds__(256) void cvt_split(
    const float* __restrict__ x, __half* __restrict__ hi,
    __half* __restrict__ lo, int n4)
{
    int i = blockIdx.x * 256 + threadIdx.x;
    if (i >= n4) return;
    float4 v = ((const float4*)x)[i];
    __half h0 = __float2half_rn(v.x), h1 = __float2half_rn(v.y);
    __half h2 = __float2half_rn(v.z), h3 = __float2half_rn(v.w);
    __half l0 = __float2half_rn(v.x - __half2float(h0));
    __half l1 = __float2half_rn(v.y - __half2float(h1));
    __half l2 = __float2half_rn(v.z - __half2float(h2));
    __half l3 = __float2half_rn(v.w - __half2float(h3));
    union { __half2 h2v[2]; uint2 u; } H, L;
    H.h2v[0] = __halves2half2(h0, h1); H.h2v[1] = __halves2half2(h2, h3);
    L.h2v[0] = __halves2half2(l0, l1); L.h2v[1] = __halves2half2(l2, l3);
    ((uint2*)hi)[i] = H.u;
    ((uint2*)lo)[i] = L.u;
}

// ---------------- prep: W [K][N] fp32 -> W^T [N][K] fp16 ----------------
__global__ __launch_bounds__(256) void tr_half(
    const float* __restrict__ W, __half* __restrict__ out, int K, int N)
{
    __shared__ float t[32][33];
    int n0 = blockIdx.x * 32, k0 = blockIdx.y * 32;
    int tx = threadIdx.x, ty = threadIdx.y;
#pragma unroll
    for (int j = 0; j < 4; ++j)
        t[ty + j * 8][tx] = W[(size_t)(k0 + ty + j * 8) * N + n0 + tx];
    __syncthreads();
#pragma unroll
    for (int j = 0; j < 4; ++j) {
        int n = ty + j * 8;
        out[(size_t)(n0 + n) * K + k0 + tx] = __float2half_rn(t[tx][n]);
    }
}

// ---------------- mma.sync GEMM: 128x128 CTA, 256 threads, BK=64, 2-stage, 2 CTA/SM ----------------
#define SSTR   144
#define SZ_A   (128 * SSTR)
#define SZ_B   (128 * SSTR)
#define BUF_SZ (2 * SZ_A + SZ_B)
#define GT_SMEM (2 * BUF_SZ)

template<int ITERS>
__device__ __forceinline__ void cpa_stage(uint32_t sdst, const char* g, int Kb, int tid) {
#pragma unroll
    for (int i = 0; i < ITERS; ++i) {
        int idx = tid + i * 256;
        int row = idx >> 3;
        int q   = (idx & 7) << 4;
        uint32_t d = sdst + row * SSTR + q;
        const char* s = g + (size_t)row * Kb + q;
        asm volatile("cp.async.cg.shared.global [%0], [%1], 16;" :: "r"(d), "l"(s));
    }
}

template<int USE_LO>
__global__ __launch_bounds__(256, 2) void gemm_tc(
    const __half* __restrict__ Ahi, const __half* __restrict__ Alo,
    const __half* __restrict__ B, float* __restrict__ C, int N, int K)
{
    extern __shared__ __align__(128) char smem[];
    const uint32_t sb = smem_to_u32(smem);

    const int tid  = threadIdx.x;
    const int wid  = tid >> 5;
    const int lane = tid & 31;
    const int bm   = blockIdx.x * 128;
    const int bn   = blockIdx.y * 128;
    const int wm   = (wid >> 1) * 32;
    const int wn   = (wid & 1) * 64;
    const int Kb   = K * 2;

    const char* gAh = (const char*)(Ahi + (size_t)bm * K);
    const char* gAl = (const char*)(Alo + (size_t)bm * K);
    const char* gB  = (const char*)(B   + (size_t)bn * K);

    float acc[2][8][4];
#pragma unroll
    for (int i = 0; i < 2; ++i)
#pragma unroll
        for (int j = 0; j < 8; ++j)
#pragma unroll
            for (int r = 0; r < 4; ++r) acc[i][j][r] = 0.0f;

    const uint32_t aoff = (lane & 15) * SSTR + ((lane >> 4) << 4);
    const uint32_t boff = ((lane & 7) + ((lane >> 4) << 3)) * SSTR + (((lane >> 3) & 1) << 4);

    const int nk = K >> 6;

    {
        uint32_t sbuf = sb;
        cpa_stage<4>(sbuf,            gAh, Kb, tid);
        if (USE_LO) cpa_stage<4>(sbuf + SZ_A, gAl, Kb, tid);
        cpa_stage<4>(sbuf + 2 * SZ_A, gB,  Kb, tid);
        asm volatile("cp.async.commit_group;");
    }

    for (int kt = 0; kt < nk; ++kt) {
        asm volatile("cp.async.wait_group 0;");
        __syncthreads();

        if (kt + 1 < nk) {
            uint32_t sbuf = sb + ((kt + 1) & 1) * BUF_SZ;
            size_t ko = (size_t)(kt + 1) * 128;
            cpa_stage<4>(sbuf,            gAh + ko, Kb, tid);
            if (USE_LO) cpa_stage<4>(sbuf + SZ_A, gAl + ko, Kb, tid);
            cpa_stage<4>(sbuf + 2 * SZ_A, gB  + ko, Kb, tid);
            asm volatile("cp.async.commit_group;");
        }

        const uint32_t sAh = sb + (kt & 1) * BUF_SZ;
        const uint32_t sAl = sAh + SZ_A;
        const uint32_t sB  = sAh + 2 * SZ_A;

#pragma unroll
        for (int ks = 0; ks < 4; ++ks) {
            const uint32_t kb = ks * 32;
            uint32_t ah[2][4], al[2][4];
#pragma unroll
            for (int mt = 0; mt < 2; ++mt) {
                uint32_t base = (wm + mt * 16) * SSTR + aoff + kb;
                ldsm4(ah[mt][0], ah[mt][1], ah[mt][2], ah[mt][3], sAh + base);
                if (USE_LO)
                    ldsm4(al[mt][0], al[mt][1], al[mt][2], al[mt][3], sAl + base);
            }
#pragma unroll
            for (int pr = 0; pr < 4; ++pr) {
                uint32_t bbase = (wn + pr * 16) * SSTR + boff + kb;
                uint32_t h0, h1, h2, h3;
                ldsm4(h0, h1, h2, h3, sB + bbase);
                uint32_t b0[2] = {h0, h1}, b1[2] = {h2, h3};
#pragma unroll
                for (int mt = 0; mt < 2; ++mt) {
                    mma16816(acc[mt][2 * pr],     ah[mt], b0);
                    mma16816(acc[mt][2 * pr + 1], ah[mt], b1);
                    if (USE_LO) {
                        mma16816(acc[mt][2 * pr],     al[mt], b0);
                        mma16816(acc[mt][2 * pr + 1], al[mt], b1);
                    }
                }
            }
        }
    }

    const int g  = lane >> 2;
    const int tg = lane & 3;
#pragma unroll
    for (int mt = 0; mt < 2; ++mt) {
#pragma unroll
        for (int nt = 0; nt < 8; ++nt) {
            const float* d = acc[mt][nt];
            size_t r = (size_t)(bm + wm + mt * 16 + g) * N + bn + wn + nt * 8 + tg * 2;
            *(float2*)&C[r] = make_float2(d[0], d[1]);
            *(float2*)&C[r + 8 * (size_t)N] = make_float2(d[2], d[3]);
        }
    }
}

// ---------------- tiled small GEMM: ba = h @ W_ba (2048x64, K=2048) ----------------
__global__ __launch_bounds__(256) void gemm_ba(
    const float* __restrict__ A, const float* __restrict__ B, float* __restrict__ C)
{
    __shared__ float sh[64][65];
    __shared__ float sB[64][65];
    const int tid = threadIdx.x;
    const int col = tid & 63;
    const int rg  = tid >> 6;
    const int br  = blockIdx.x * 64;

    float acc[16];
#pragma unroll
    for (int r = 0; r < 16; ++r) acc[r] = 0.0f;

    for (int kt = 0; kt < HID / 64; ++kt) {
#pragma unroll
        for (int i = 0; i < 16; ++i) {
            int idx = tid + i * 256;
            int row = idx >> 6, kk = idx & 63;
            sh[row][kk] = A[(size_t)(br + row) * HID + kt * 64 + kk];
            sB[row][kk] = B[(size_t)(kt * 64 + row) * 64 + kk];
        }
        __syncthreads();
#pragma unroll 16
        for (int kk = 0; kk < 64; ++kk) {
            float b = sB[kk][col];
#pragma unroll
            for (int r = 0; r < 16; ++r)
                acc[r] = fmaf(sh[rg * 16 + r][kk], b, acc[r]);
        }
        __syncthreads();
    }
#pragma unroll
    for (int r = 0; r < 16; ++r)
        C[(size_t)(br + rg * 16 + r) * 64 + col] = acc[r];
}

// ---------------- causal depthwise conv (K=4) + SiLU, 4 t per thread ----------------
__global__ __launch_bounds__(256) void conv_silu(
    const float* __restrict__ qkvz, const float* __restrict__ conv_w,
    float* __restrict__ out)
{
    int idx = blockIdx.x * blockDim.x + threadIdx.x;
    if (idx >= (T_SEQ / 4) * CONV_DIM) return;
    int tq = idx >> 13;
    int c  = idx & (CONV_DIM - 1);
    int t0 = tq * 4;
    const float* w = conv_w + c * 4;
    float xv[7];
#pragma unroll
    for (int j = 0; j < 7; ++j) {
        int tt = t0 - 3 + j;
        xv[j] = (tt >= 0) ? qkvz[(size_t)tt * QKVZ_N + c] : 0.0f;
    }
#pragma unroll
    for (int i = 0; i < 4; ++i) {
        float a = w[0] * xv[i];
        a = fmaf(w[1], xv[i + 1], a);
        a = fmaf(w[2], xv[i + 2], a);
        a = fmaf(w[3], xv[i + 3], a);
        out[(size_t)(t0 + i) * CONV_DIM + c] = siluf_(a);
    }
}

// ---------------- gating ----------------
__global__ __launch_bounds__(256) void gate_prep(
    const float* __restrict__ ba, const float* __restrict__ A_log,
    const float* __restrict__ dt_bias, float2* __restrict__ egbeta)
{
    int i = blockIdx.x * blockDim.x + threadIdx.x;
    if (i >= T_SEQ * NUM_V) return;
    int t = i >> 5;
    int h = i & 31;
    float b = ba[(size_t)t * 64 + h];
    float a = ba[(size_t)t * 64 + 32 + h];
    float x = a + dt_bias[h];
    float sp = (x > 20.0f) ? x : log1pf(expf(x));
    float g = -expf(A_log[h]) * sp;
    egbeta[i] = make_float2(expf(g), sigmoidf_(b));
}

// ---------------- fused l2norm(q,k) + qk dot: one warp per (t, key-head) ----------------
__global__ __launch_bounds__(256) void l2norm_qk_dot(
    const float* __restrict__ qkv, float* __restrict__ qhat,
    float* __restrict__ khat, float* __restrict__ qkdot)
{
    int gid  = blockIdx.x * 8 + (threadIdx.x >> 5);
    int lane = threadIdx.x & 31;
    int t  = gid >> 4;
    int kh = gid & 15;
    const float* qsrc = qkv + (size_t)t * CONV_DIM + kh * DK;
    float4 q = *((const float4*)qsrc + lane);
    float4 k = *((const float4*)(qsrc + KEY_DIM) + lane);
    float sq  = q.x * q.x + q.y * q.y + q.z * q.z + q.w * q.w;
    float sk  = k.x * k.x + k.y * k.y + k.z * k.z + k.w * k.w;
    float sqk = q.x * k.x + q.y * k.y + q.z * k.z + q.w * k.w;
#pragma unroll
    for (int off = 16; off > 0; off >>= 1) {
        sq  += __shfl_xor_sync(0xffffffffu, sq,  off);
        sk  += __shfl_xor_sync(0xffffffffu, sk,  off);
        sqk += __shfl_xor_sync(0xffffffffu, sqk, off);
    }
    float rq = rsqrtf(sq + 1e-6f) * QSCALE;
    float rk = rsqrtf(sk + 1e-6f);
    size_t base = (size_t)t * KEY_DIM + kh * DK;
    *((float4*)(qhat + base) + lane) = make_float4(q.x * rq, q.y * rq, q.z * rq, q.w * rq);
    *((float4*)(khat + base) + lane) = make_float4(k.x * rk, k.y * rk, k.z * rk, k.w * rk);
    if (lane == 0) qkdot[t * NUM_K + kh] = sqk * rq * rk;
}

// ---------------- gated delta scan: smem-staged, 8 warps, 4 cols/warp (2 halves x 2 ILP) ----
// CTA = (head, 32-col group); grid 128; 256 threads. Chunks of 32 timesteps via cp.async.
// smem per buffer (bytes): K 16384 | Q 16384 | V 4096 | EB 256 | XQ 128 -> pad 37376
#define SC_TC   32
#define SC_QB   16384
#define SC_VB   32768
#define SC_EB   36864
#define SC_XB   37120
#define SC_BUF  37376
#define SC_SMEM (2 * SC_BUF)

__device__ __forceinline__ void scan_stage(
    uint32_t sbase, const float* kb_, const float* qb_,
    const float* vb_, const float* eb_, const float* xb_, int tid)
{
    // k/q: j = 0..31 float4s per row; even j at [0,256)B, odd j at [256,512)B
#pragma unroll
    for (int i = 0; i < 8; ++i) {
        int idx = tid + i * 256;          // 0..2047
        int isq = idx >> 10;
        int r   = idx & 1023;
        int tt  = r >> 5;
        int j   = r & 31;
        const float* src = (isq ? qb_ : kb_) + (size_t)tt * KEY_DIM + j * 4;
        uint32_t dst = sbase + (isq ? SC_QB : 0) + tt * 512 + ((j & 1) << 8) + ((j >> 1) << 4);
        asm volatile("cp.async.ca.shared.global [%0], [%1], 16;" :: "r"(dst), "l"(src));
    }
    {                                     // v: 32 floats per tt = 8 float4, 256 total
        int tt = tid >> 3, j = tid & 7;
        const float* src = vb_ + (size_t)tt * CONV_DIM + j * 4;
        uint32_t dst = sbase + SC_VB + tt * 128 + j * 16;
        asm volatile("cp.async.ca.shared.global [%0], [%1], 16;" :: "r"(dst), "l"(src));
    }
    if (tid < 32) {                       // egbeta: float2 per tt
        const float* src = eb_ + (size_t)tid * (2 * NUM_V);
        uint32_t dst = sbase + SC_EB + tid * 8;
        asm volatile("cp.async.ca.shared.global [%0], [%1], 8;" :: "r"(dst), "l"(src));
    } else if (tid < 64) {                // qkdot: float per tt
        int tt = tid - 32;
        const float* src = xb_ + (size_t)tt * NUM_K;
        uint32_t dst = sbase + SC_XB + tt * 4;
        asm volatile("cp.async.ca.shared.global [%0], [%1], 4;" :: "r"(dst), "l"(src));
    }
}

__global__ __launch_bounds__(256) void gdn_scan(
    const float* __restrict__ qhat, const float* __restrict__ khat,
    const float* __restrict__ qkv, const float* __restrict__ egbeta,
    const float* __restrict__ qk, float* __restrict__ o)
{
    extern __shared__ __align__(128) char ssm[];
    const uint32_t sbase = smem_to_u32(ssm);
    const float* sf = (const float*)ssm;

    const int tid  = threadIdx.x;
    const int warp = tid >> 5;                  // 0..7
    const int lane = tid & 31;
    const int half = lane >> 4;
    const int sl   = lane & 15;
    const int h    = blockIdx.x >> 2;           // 32 heads x 4 groups
    const int cb   = (blockIdx.x & 3) * 32;     // column base
    const int ci   = warp * 4 + half * 2;       // first of this half's 2 columns
    const int kh   = h >> 1;

    const float* kb_ = khat + kh * DK;
    const float* qb_ = qhat + kh * DK;
    const float* vb_ = qkv + 2 * KEY_DIM + h * DV + cb;
    const float* eb_ = egbeta + 2 * h;
    const float* xb_ = qk + kh;
    float*       op  = o + h * DV + cb + ci;

    const int NC = T_SEQ / SC_TC;                // 64

    // two columns' states per thread (A = ci, B = ci+1)
    float4 SaA = make_float4(0.f,0.f,0.f,0.f), SbA = make_float4(0.f,0.f,0.f,0.f);
    float4 SaB = make_float4(0.f,0.f,0.f,0.f), SbB = make_float4(0.f,0.f,0.f,0.f);

    scan_stage(sbase, kb_, qb_, vb_, eb_, xb_, tid);
    asm volatile("cp.async.commit_group;");

    for (int c = 0; c < NC; ++c) {
        if (c + 1 < NC) {
            size_t adv = (size_t)(c + 1) * SC_TC;
            scan_stage(sbase + ((c + 1) & 1) * SC_BUF,
                       kb_ + adv * KEY_DIM, qb_ + adv * KEY_DIM,
                       vb_ + adv * CONV_DIM, eb_ + adv * 2 * NUM_V,
                       xb_ + adv * NUM_K, tid);
            asm volatile("cp.async.commit_group;");
            asm volatile("cp.async.wait_group 1;");
        } else {
            asm volatile("cp.async.wait_group 0;");
        }
        __syncthreads();

        const int bo = (c & 1) * (SC_BUF / 4);
        for (int tt = 0; tt < SC_TC; ++tt) {
            const float* kr = sf + bo + tt * 128;
            const float* qr = sf + bo + SC_QB / 4 + tt * 128;
            float4 k0 = *(const float4*)(kr + sl * 4);
            float4 k1 = *(const float4*)(kr + 64 + sl * 4);
            float4 q0 = *(const float4*)(qr + sl * 4);
            float4 q1 = *(const float4*)(qr + 64 + sl * 4);
            float  vtA = sf[bo + SC_VB / 4 + tt * 32 + ci];
            float  vtB = sf[bo + SC_VB / 4 + tt * 32 + ci + 1];
            float  eg = sf[bo + SC_EB / 4 + tt * 2];
            float  bt = sf[bo + SC_EB / 4 + tt * 2 + 1];
            float  xq = sf[bo + SC_XB / 4 + tt];

            float dkA = k0.x*SaA.x + k0.y*SaA.y + k0.z*SaA.z + k0.w*SaA.w
                      + k1.x*SbA.x + k1.y*SbA.y + k1.z*SbA.z + k1.w*SbA.w;
            float dqA = q0.x*SaA.x + q0.y*SaA.y + q0.z*SaA.z + q0.w*SaA.w
                      + q1.x*SbA.x + q1.y*SbA.y + q1.z*SbA.z + q1.w*SbA.w;
            float dkB = k0.x*SaB.x + k0.y*SaB.y + k0.z*SaB.z + k0.w*SaB.w
                      + k1.x*SbB.x + k1.y*SbB.y + k1.z*SbB.z + k1.w*SbB.w;
            float dqB = q0.x*SaB.x + q0.y*SaB.y + q0.z*SaB.z + q0.w*SaB.w
                      + q1.x*SbB.x + q1.y*SbB.y + q1.z*SbB.z + q1.w*SbB.w;
#pragma unroll
            for (int off = 8; off > 0; off >>= 1) {
                dkA += __shfl_xor_sync(0xffffffffu, dkA, off);
                dkB += __shfl_xor_sync(0xffffffffu, dkB, off);
                dqA += __shfl_xor_sync(0xffffffffu, dqA, off);
                dqB += __shfl_xor_sync(0xffffffffu, dqB, off);
            }
            const float deltaA = (vtA - eg * dkA) * bt;
            const float deltaB = (vtB - eg * dkB) * bt;
            const float otA    = fmaf(eg, dqA, xq * deltaA);
            const float otB    = fmaf(eg, dqB, xq * deltaB);
            SaA.x = fmaf(SaA.x, eg, k0.x * deltaA);
            SaA.y = fmaf(SaA.y, eg, k0.y * deltaA);
            SaA.z = fmaf(SaA.z, eg, k0.z * deltaA);
            SaA.w = fmaf(SaA.w, eg, k0.w * deltaA);
            SbA.x = fmaf(SbA.x, eg, k1.x * deltaA);
            SbA.y = fmaf(SbA.y, eg, k1.y * deltaA);
            SbA.z = fmaf(SbA.z, eg, k1.z * deltaA);
            SbA.w = fmaf(SbA.w, eg, k1.w * deltaA);
            SaB.x = fmaf(SaB.x, eg, k0.x * deltaB);
            SaB.y = fmaf(SaB.y, eg, k0.y * deltaB);
            SaB.z = fmaf(SaB.z, eg, k0.z * deltaB);
            SaB.w = fmaf(SaB.w, eg, k0.w * deltaB);
            SbB.x = fmaf(SbB.x, eg, k1.x * deltaB);
            SbB.y = fmaf(SbB.y, eg, k1.y * deltaB);
            SbB.z = fmaf(SbB.z, eg, k1.z * deltaB);
            SbB.w = fmaf(SbB.w, eg, k1.w * deltaB);
            if (sl == 0)
                *(float2*)&op[(size_t)(c * SC_TC + tt) * VAL_DIM] = make_float2(otA, otB);
        }
        __syncthreads();
    }
}

// ---------------- RMSNorm * norm_w * silu(z), write fp16 hi/lo directly ----------------
__global__ __launch_bounds__(256) void rms_gate_split(
    const float* __restrict__ o, const float* __restrict__ qkvz,
    const float* __restrict__ norm_w,
    __half* __restrict__ hi, __half* __restrict__ lo)
{
    int gid  = blockIdx.x * 8 + (threadIdx.x >> 5);
    int lane = threadIdx.x & 31;
    int t = gid >> 5;
    int h = gid & 31;
    const float* orow = o + (size_t)t * VAL_DIM + h * DV;
    float4 x = *(const float4*)(orow + lane * 4);
    float s = x.x * x.x + x.y * x.y + x.z * x.z + x.w * x.w;
#pragma unroll
    for (int off = 16; off > 0; off >>= 1) s += __shfl_xor_sync(0xffffffffu, s, off);
    float r = rsqrtf(s * (1.0f / DV) + 1e-6f);
    float4 z  = *(const float4*)(qkvz + (size_t)t * QKVZ_N + 2 * KEY_DIM + VAL_DIM + h * DV + lane * 4);
    float4 nw = *(const float4*)(norm_w + lane * 4);
    float4 y;
    y.x = x.x * r * nw.x * siluf_(z.x);
    y.y = x.y * r * nw.y * siluf_(z.y);
    y.z = x.z * r * nw.z * siluf_(z.z);
    y.w = x.w * r * nw.w * siluf_(z.w);
    __half h0 = __float2half_rn(y.x), h1 = __float2half_rn(y.y);
    __half h2 = __float2half_rn(y.z), h3 = __float2half_rn(y.w);
    __half l0 = __float2half_rn(y.x - __half2float(h0));
    __half l1 = __float2half_rn(y.y - __half2float(h1));
    __half l2 = __float2half_rn(y.z - __half2float(h2));
    __half l3 = __float2half_rn(y.w - __half2float(h3));
    union { __half2 h2v[2]; uint2 u; } H, L;
    H.h2v[0] = __halves2half2(h0, h1); H.h2v[1] = __halves2half2(h2, h3);
    L.h2v[0] = __halves2half2(l0, l1); L.h2v[1] = __halves2half2(l2, l3);
    int i4 = (t * VAL_DIM + h * DV) / 4 + lane;
    ((uint2*)hi)[i4] = H.u;
    ((uint2*)lo)[i4] = L.u;
}

// ---------------- launch ----------------
extern "C" void kernel_launch(void* const* d_in, const int* in_sizes, int n_in,
                              void* d_out, int out_size)
{
    const float* h_in    = (const float*)d_in[0];
    const float* W_qkvz  = (const float*)d_in[1];
    const float* W_ba    = (const float*)d_in[2];
    const float* conv_w  = (const float*)d_in[3];
    const float* dt_bias = (const float*)d_in[4];
    const float* A_log   = (const float*)d_in[5];
    const float* norm_w  = (const float*)d_in[6];
    const float* W_out   = (const float*)d_in[7];
    float* out = (float*)d_out;

    float *qkvz, *qkv, *ba, *qhat, *khat, *qkdot, *oscan;
    float2* egbeta;
    __half *Wq, *Wo, *A_hi, *A_lo;
    cudaGetSymbolAddress((void**)&qkvz,   g_qkvz);
    cudaGetSymbolAddress((void**)&qkv,    g_qkv);
    cudaGetSymbolAddress((void**)&ba,     g_ba);
    cudaGetSymbolAddress((void**)&egbeta, g_egbeta);
    cudaGetSymbolAddress((void**)&qhat,   g_qhat);
    cudaGetSymbolAddress((void**)&khat,   g_khat);
    cudaGetSymbolAddress((void**)&qkdot,  g_qkdot);
    cudaGetSymbolAddress((void**)&oscan,  g_oscan);
    cudaGetSymbolAddress((void**)&Wq,     g_Wq);
    cudaGetSymbolAddress((void**)&Wo,     g_Wo);
    cudaGetSymbolAddress((void**)&A_hi,   g_A_hi);
    cudaGetSymbolAddress((void**)&A_lo,   g_A_lo);

    cudaFuncSetAttribute(gemm_tc<1>, cudaFuncAttributeMaxDynamicSharedMemorySize, GT_SMEM);
    cudaFuncSetAttribute(gemm_tc<0>, cudaFuncAttributeMaxDynamicSharedMemorySize, GT_SMEM);
    cudaFuncSetAttribute(gdn_scan, cudaFuncAttributeMaxDynamicSharedMemorySize, SC_SMEM);

    // prep
    {
        dim3 blk(32, 8);
        tr_half<<<dim3(QKVZ_N / 32, HID / 32), blk>>>(W_qkvz, Wq, HID, QKVZ_N);
        tr_half<<<dim3(HID / 32, VAL_DIM / 32), blk>>>(W_out, Wo, VAL_DIM, HID);
    }
    cvt_split<<<(T_SEQ * HID / 4 + 255) / 256, 256>>>(h_in, A_hi, A_lo, T_SEQ * HID / 4);

    // GEMM1: qkvz = h @ W_qkvz   [2048 x 12288], K=2048 (split-A, 2 passes)
    gemm_tc<1><<<dim3(T_SEQ / 128, QKVZ_N / 128), 256, GT_SMEM>>>(A_hi, A_lo, Wq, qkvz, QKVZ_N, HID);

    gemm_ba<<<T_SEQ / 64, 256>>>(h_in, W_ba, ba);
    conv_silu<<<((T_SEQ / 4) * CONV_DIM) / 256, 256>>>(qkvz, conv_w, qkv);
    gate_prep<<<(T_SEQ * NUM_V) / 256, 256>>>(ba, A_log, dt_bias, egbeta);
    l2norm_qk_dot<<<(T_SEQ * NUM_K) / 8, 256>>>(qkv, qhat, khat, qkdot);
    gdn_scan<<<NUM_V * 4, 256, SC_SMEM>>>(qhat, khat, qkv, (const float*)egbeta, qkdot, oscan);
    rms_gate_split<<<(T_SEQ * NUM_V) / 8, 256>>>(oscan, qkvz, norm_w, A_hi, A_lo);

    // GEMM2: out = gated @ W_out  [2048 x 2048], K=4096 (single-pass fp16 A)
    gemm_tc<0><<<dim3(T_SEQ / 128, HID / 128), 256, GT_SMEM>>>(A_hi, A_lo, Wo, out, HID, VAL_DIM);
}

// round 17
// speedup vs baseline: 2.9670x; 1.1788x over previous
#include <cuda_runtime.h>
#include <cuda_fp16.h>
#include <math.h>
#include <stdint.h>

// ---------------- problem constants ----------------
#define T_SEQ   2048
#define HID     2048
#define NUM_K   16
#define NUM_V   32
#define DK      128
#define DV      128
#define KEY_DIM 2048
#define VAL_DIM 4096
#define CONV_DIM 8192
#define QKVZ_N  12288
#define QSCALE  0.08838834764831845f

// ---------------- scratch ----------------
__device__ float  g_qkvz  [T_SEQ * QKVZ_N];
__device__ float  g_qkv   [T_SEQ * CONV_DIM];
__device__ float  g_ba    [T_SEQ * 64];
__device__ float2 g_egbeta[T_SEQ * NUM_V];
__device__ float  g_qhat  [T_SEQ * KEY_DIM];
__device__ float  g_khat  [T_SEQ * KEY_DIM];
__device__ float  g_qkdot [T_SEQ * NUM_K];
__device__ float  g_oscan [T_SEQ * VAL_DIM];

// fp16 operands: weights single fp16 (W^T), activations single fp16
__device__ __half g_Wq[QKVZ_N * HID];
__device__ __half g_Wo[HID * VAL_DIM];
__device__ __half g_A_hi[T_SEQ * VAL_DIM];

// ---------------- helpers ----------------
__device__ __forceinline__ float sigmoidf_(float x) { return 1.0f / (1.0f + __expf(-x)); }
__device__ __forceinline__ float siluf_(float x)    { return x * sigmoidf_(x); }

__device__ __forceinline__ uint32_t smem_to_u32(const void* p) {
    uint32_t a;
    asm("{ .reg .u64 t; cvta.to.shared.u64 t, %1; cvt.u32.u64 %0, t; }" : "=r"(a) : "l"(p));
    return a;
}
__device__ __forceinline__ void ldsm4(uint32_t& r0, uint32_t& r1, uint32_t& r2, uint32_t& r3,
                                      uint32_t addr) {
    asm volatile("ldmatrix.sync.aligned.m8n8.x4.shared.b16 {%0,%1,%2,%3}, [%4];"
                 : "=r"(r0), "=r"(r1), "=r"(r2), "=r"(r3) : "r"(addr));
}
__device__ __forceinline__ void mma16816(float* d, const uint32_t* a, const uint32_t* b) {
    asm volatile("mma.sync.aligned.m16n8k16.row.col.f32.f16.f16.f32 "
                 "{%0,%1,%2,%3}, {%4,%5,%6,%7}, {%8,%9}, {%0,%1,%2,%3};"
                 : "+f"(d[0]), "+f"(d[1]), "+f"(d[2]), "+f"(d[3])
                 : "r"(a[0]), "r"(a[1]), "r"(a[2]), "r"(a[3]), "r"(b[0]), "r"(b[1]));
}

// ---------------- prep: fp32 -> fp16 ----------------
__global__ __launch_bounds__(256) void cvt_half(
    const float* __restrict__ x, __half* __restrict__ hi, int n4)
{
    int i = blockIdx.x * 256 + threadIdx.x;
    if (i >= n4) return;
    float4 v = ((const float4*)x)[i];
    union { __half2 h2v[2]; uint2 u; } H;
    H.h2v[0] = __halves2half2(__float2half_rn(v.x), __float2half_rn(v.y));
    H.h2v[1] = __halves2half2(__float2half_rn(v.z), __float2half_rn(v.w));
    ((uint2*)hi)[i] = H.u;
}

// ---------------- prep: W [K][N] fp32 -> W^T [N][K] fp16 ----------------
__global__ __launch_bounds__(256) void tr_half(
    const float* __restrict__ W, __half* __restrict__ out, int K, int N)
{
    __shared__ float t[32][33];
    int n0 = blockIdx.x * 32, k0 = blockIdx.y * 32;
    int tx = threadIdx.x, ty = threadIdx.y;
#pragma unroll
    for (int j = 0; j < 4; ++j)
        t[ty + j * 8][tx] = W[(size_t)(k0 + ty + j * 8) * N + n0 + tx];
    __syncthreads();
#pragma unroll
    for (int j = 0; j < 4; ++j) {
        int n = ty + j * 8;
        out[(size_t)(n0 + n) * K + k0 + tx] = __float2half_rn(t[tx][n]);
    }
}

// ---------------- mma.sync GEMM: 128x128 CTA, 256 threads, BK=64, 2-stage, 2 CTA/SM ----------------
#define SSTR   144
#define SZ_A   (128 * SSTR)
#define SZ_B   (128 * SSTR)
#define BUF_SZ (SZ_A + SZ_B)
#define GT_SMEM (2 * BUF_SZ)

template<int ITERS>
__device__ __forceinline__ void cpa_stage(uint32_t sdst, const char* g, int Kb, int tid) {
#pragma unroll
    for (int i = 0; i < ITERS; ++i) {
        int idx = tid + i * 256;
        int row = idx >> 3;
        int q   = (idx & 7) << 4;
        uint32_t d = sdst + row * SSTR + q;
        const char* s = g + (size_t)row * Kb + q;
        asm volatile("cp.async.cg.shared.global [%0], [%1], 16;" :: "r"(d), "l"(s));
    }
}

__global__ __launch_bounds__(256, 2) void gemm_tc(
    const __half* __restrict__ A, const __half* __restrict__ B,
    float* __restrict__ C, int N, int K)
{
    extern __shared__ __align__(128) char smem[];
    const uint32_t sb = smem_to_u32(smem);

    const int tid  = threadIdx.x;
    const int wid  = tid >> 5;
    const int lane = tid & 31;
    const int bm   = blockIdx.x * 128;
    const int bn   = blockIdx.y * 128;
    const int wm   = (wid >> 1) * 32;
    const int wn   = (wid & 1) * 64;
    const int Kb   = K * 2;

    const char* gA = (const char*)(A + (size_t)bm * K);
    const char* gB = (const char*)(B + (size_t)bn * K);

    float acc[2][8][4];
#pragma unroll
    for (int i = 0; i < 2; ++i)
#pragma unroll
        for (int j = 0; j < 8; ++j)
#pragma unroll
            for (int r = 0; r < 4; ++r) acc[i][j][r] = 0.0f;

    const uint32_t aoff = (lane & 15) * SSTR + ((lane >> 4) << 4);
    const uint32_t boff = ((lane & 7) + ((lane >> 4) << 3)) * SSTR + (((lane >> 3) & 1) << 4);

    const int nk = K >> 6;

    {
        cpa_stage<4>(sb,        gA, Kb, tid);
        cpa_stage<4>(sb + SZ_A, gB, Kb, tid);
        asm volatile("cp.async.commit_group;");
    }

    for (int kt = 0; kt < nk; ++kt) {
        asm volatile("cp.async.wait_group 0;");
        __syncthreads();

        if (kt + 1 < nk) {
            uint32_t sbuf = sb + ((kt + 1) & 1) * BUF_SZ;
            size_t ko = (size_t)(kt + 1) * 128;
            cpa_stage<4>(sbuf,        gA + ko, Kb, tid);
            cpa_stage<4>(sbuf + SZ_A, gB + ko, Kb, tid);
            asm volatile("cp.async.commit_group;");
        }

        const uint32_t sA = sb + (kt & 1) * BUF_SZ;
        const uint32_t sB = sA + SZ_A;

#pragma unroll
        for (int ks = 0; ks < 4; ++ks) {
            const uint32_t kb = ks * 32;
            uint32_t ah[2][4];
#pragma unroll
            for (int mt = 0; mt < 2; ++mt) {
                uint32_t base = (wm + mt * 16) * SSTR + aoff + kb;
                ldsm4(ah[mt][0], ah[mt][1], ah[mt][2], ah[mt][3], sA + base);
            }
#pragma unroll
            for (int pr = 0; pr < 4; ++pr) {
                uint32_t bbase = (wn + pr * 16) * SSTR + boff + kb;
                uint32_t h0, h1, h2, h3;
                ldsm4(h0, h1, h2, h3, sB + bbase);
                uint32_t b0[2] = {h0, h1}, b1[2] = {h2, h3};
#pragma unroll
                for (int mt = 0; mt < 2; ++mt) {
                    mma16816(acc[mt][2 * pr],     ah[mt], b0);
                    mma16816(acc[mt][2 * pr + 1], ah[mt], b1);
                }
            }
        }
    }

    const int g  = lane >> 2;
    const int tg = lane & 3;
#pragma unroll
    for (int mt = 0; mt < 2; ++mt) {
#pragma unroll
        for (int nt = 0; nt < 8; ++nt) {
            const float* d = acc[mt][nt];
            size_t r = (size_t)(bm + wm + mt * 16 + g) * N + bn + wn + nt * 8 + tg * 2;
            *(float2*)&C[r] = make_float2(d[0], d[1]);
            *(float2*)&C[r + 8 * (size_t)N] = make_float2(d[2], d[3]);
        }
    }
}

// ---------------- tiled small GEMM: ba = h @ W_ba (2048x64, K=2048) ----------------
__global__ __launch_bounds__(256) void gemm_ba(
    const float* __restrict__ A, const float* __restrict__ B, float* __restrict__ C)
{
    __shared__ float sh[64][65];
    __shared__ float sB[64][65];
    const int tid = threadIdx.x;
    const int col = tid & 63;
    const int rg  = tid >> 6;
    const int br  = blockIdx.x * 64;

    float acc[16];
#pragma unroll
    for (int r = 0; r < 16; ++r) acc[r] = 0.0f;

    for (int kt = 0; kt < HID / 64; ++kt) {
#pragma unroll
        for (int i = 0; i < 16; ++i) {
            int idx = tid + i * 256;
            int row = idx >> 6, kk = idx & 63;
            sh[row][kk] = A[(size_t)(br + row) * HID + kt * 64 + kk];
            sB[row][kk] = B[(size_t)(kt * 64 + row) * 64 + kk];
        }
        __syncthreads();
#pragma unroll 16
        for (int kk = 0; kk < 64; ++kk) {
            float b = sB[kk][col];
#pragma unroll
            for (int r = 0; r < 16; ++r)
                acc[r] = fmaf(sh[rg * 16 + r][kk], b, acc[r]);
        }
        __syncthreads();
    }
#pragma unroll
    for (int r = 0; r < 16; ++r)
        C[(size_t)(br + rg * 16 + r) * 64 + col] = acc[r];
}

// ---------------- causal depthwise conv (K=4) + SiLU, 4 t per thread ----------------
__global__ __launch_bounds__(256) void conv_silu(
    const float* __restrict__ qkvz, const float* __restrict__ conv_w,
    float* __restrict__ out)
{
    int idx = blockIdx.x * blockDim.x + threadIdx.x;
    if (idx >= (T_SEQ / 4) * CONV_DIM) return;
    int tq = idx >> 13;
    int c  = idx & (CONV_DIM - 1);
    int t0 = tq * 4;
    const float* w = conv_w + c * 4;
    float xv[7];
#pragma unroll
    for (int j = 0; j < 7; ++j) {
        int tt = t0 - 3 + j;
        xv[j] = (tt >= 0) ? qkvz[(size_t)tt * QKVZ_N + c] : 0.0f;
    }
#pragma unroll
    for (int i = 0; i < 4; ++i) {
        float a = w[0] * xv[i];
        a = fmaf(w[1], xv[i + 1], a);
        a = fmaf(w[2], xv[i + 2], a);
        a = fmaf(w[3], xv[i + 3], a);
        out[(size_t)(t0 + i) * CONV_DIM + c] = siluf_(a);
    }
}

// ---------------- gating ----------------
__global__ __launch_bounds__(256) void gate_prep(
    const float* __restrict__ ba, const float* __restrict__ A_log,
    const float* __restrict__ dt_bias, float2* __restrict__ egbeta)
{
    int i = blockIdx.x * blockDim.x + threadIdx.x;
    if (i >= T_SEQ * NUM_V) return;
    int t = i >> 5;
    int h = i & 31;
    float b = ba[(size_t)t * 64 + h];
    float a = ba[(size_t)t * 64 + 32 + h];
    float x = a + dt_bias[h];
    float sp = (x > 20.0f) ? x : log1pf(expf(x));
    float g = -expf(A_log[h]) * sp;
    egbeta[i] = make_float2(expf(g), sigmoidf_(b));
}

// ---------------- fused l2norm(q,k) + qk dot: one warp per (t, key-head) ----------------
__global__ __launch_bounds__(256) void l2norm_qk_dot(
    const float* __restrict__ qkv, float* __restrict__ qhat,
    float* __restrict__ khat, float* __restrict__ qkdot)
{
    int gid  = blockIdx.x * 8 + (threadIdx.x >> 5);
    int lane = threadIdx.x & 31;
    int t  = gid >> 4;
    int kh = gid & 15;
    const float* qsrc = qkv + (size_t)t * CONV_DIM + kh * DK;
    float4 q = *((const float4*)qsrc + lane);
    float4 k = *((const float4*)(qsrc + KEY_DIM) + lane);
    float sq  = q.x * q.x + q.y * q.y + q.z * q.z + q.w * q.w;
    float sk  = k.x * k.x + k.y * k.y + k.z * k.z + k.w * k.w;
    float sqk = q.x * k.x + q.y * k.y + q.z * k.z + q.w * k.w;
#pragma unroll
    for (int off = 16; off > 0; off >>= 1) {
        sq  += __shfl_xor_sync(0xffffffffu, sq,  off);
        sk  += __shfl_xor_sync(0xffffffffu, sk,  off);
        sqk += __shfl_xor_sync(0xffffffffu, sqk, off);
    }
    float rq = rsqrtf(sq + 1e-6f) * QSCALE;
    float rk = rsqrtf(sk + 1e-6f);
    size_t base = (size_t)t * KEY_DIM + kh * DK;
    *((float4*)(qhat + base) + lane) = make_float4(q.x * rq, q.y * rq, q.z * rq, q.w * rq);
    *((float4*)(khat + base) + lane) = make_float4(k.x * rk, k.y * rk, k.z * rk, k.w * rk);
    if (lane == 0) qkdot[t * NUM_K + kh] = sqk * rq * rk;
}

// ---------------- gated delta scan: smem-staged, 8 warps, 4 cols/warp (2 halves x 2 ILP) ----
#define SC_TC   32
#define SC_QB   16384
#define SC_VB   32768
#define SC_EB   36864
#define SC_XB   37120
#define SC_BUF  37376
#define SC_SMEM (2 * SC_BUF)

__device__ __forceinline__ void scan_stage(
    uint32_t sbase, const float* kb_, const float* qb_,
    const float* vb_, const float* eb_, const float* xb_, int tid)
{
#pragma unroll
    for (int i = 0; i < 8; ++i) {
        int idx = tid + i * 256;          // 0..2047
        int isq = idx >> 10;
        int r   = idx & 1023;
        int tt  = r >> 5;
        int j   = r & 31;
        const float* src = (isq ? qb_ : kb_) + (size_t)tt * KEY_DIM + j * 4;
        uint32_t dst = sbase + (isq ? SC_QB : 0) + tt * 512 + ((j & 1) << 8) + ((j >> 1) << 4);
        asm volatile("cp.async.ca.shared.global [%0], [%1], 16;" :: "r"(dst), "l"(src));
    }
    {
        int tt = tid >> 3, j = tid & 7;
        const float* src = vb_ + (size_t)tt * CONV_DIM + j * 4;
        uint32_t dst = sbase + SC_VB + tt * 128 + j * 16;
        asm volatile("cp.async.ca.shared.global [%0], [%1], 16;" :: "r"(dst), "l"(src));
    }
    if (tid < 32) {
        const float* src = eb_ + (size_t)tid * (2 * NUM_V);
        uint32_t dst = sbase + SC_EB + tid * 8;
        asm volatile("cp.async.ca.shared.global [%0], [%1], 8;" :: "r"(dst), "l"(src));
    } else if (tid < 64) {
        int tt = tid - 32;
        const float* src = xb_ + (size_t)tt * NUM_K;
        uint32_t dst = sbase + SC_XB + tt * 4;
        asm volatile("cp.async.ca.shared.global [%0], [%1], 4;" :: "r"(dst), "l"(src));
    }
}

__global__ __launch_bounds__(256) void gdn_scan(
    const float* __restrict__ qhat, const float* __restrict__ khat,
    const float* __restrict__ qkv, const float* __restrict__ egbeta,
    const float* __restrict__ qk, float* __restrict__ o)
{
    extern __shared__ __align__(128) char ssm[];
    const uint32_t sbase = smem_to_u32(ssm);
    const float* sf = (const float*)ssm;

    const int tid  = threadIdx.x;
    const int warp = tid >> 5;
    const int lane = tid & 31;
    const int half = lane >> 4;
    const int sl   = lane & 15;
    const int h    = blockIdx.x >> 2;
    const int cb   = (blockIdx.x & 3) * 32;
    const int ci   = warp * 4 + half * 2;
    const int kh   = h >> 1;

    const float* kb_ = khat + kh * DK;
    const float* qb_ = qhat + kh * DK;
    const float* vb_ = qkv + 2 * KEY_DIM + h * DV + cb;
    const float* eb_ = egbeta + 2 * h;
    const float* xb_ = qk + kh;
    float*       op  = o + h * DV + cb + ci;

    const int NC = T_SEQ / SC_TC;

    float4 SaA = make_float4(0.f,0.f,0.f,0.f), SbA = make_float4(0.f,0.f,0.f,0.f);
    float4 SaB = make_float4(0.f,0.f,0.f,0.f), SbB = make_float4(0.f,0.f,0.f,0.f);

    scan_stage(sbase, kb_, qb_, vb_, eb_, xb_, tid);
    asm volatile("cp.async.commit_group;");

    for (int c = 0; c < NC; ++c) {
        if (c + 1 < NC) {
            size_t adv = (size_t)(c + 1) * SC_TC;
            scan_stage(sbase + ((c + 1) & 1) * SC_BUF,
                       kb_ + adv * KEY_DIM, qb_ + adv * KEY_DIM,
                       vb_ + adv * CONV_DIM, eb_ + adv * 2 * NUM_V,
                       xb_ + adv * NUM_K, tid);
            asm volatile("cp.async.commit_group;");
            asm volatile("cp.async.wait_group 1;");
        } else {
            asm volatile("cp.async.wait_group 0;");
        }
        __syncthreads();

        const int bo = (c & 1) * (SC_BUF / 4);
        for (int tt = 0; tt < SC_TC; ++tt) {
            const float* kr = sf + bo + tt * 128;
            const float* qr = sf + bo + SC_QB / 4 + tt * 128;
            float4 k0 = *(const float4*)(kr + sl * 4);
            float4 k1 = *(const float4*)(kr + 64 + sl * 4);
            float4 q0 = *(const float4*)(qr + sl * 4);
            float4 q1 = *(const float4*)(qr + 64 + sl * 4);
            float  vtA = sf[bo + SC_VB / 4 + tt * 32 + ci];
            float  vtB = sf[bo + SC_VB / 4 + tt * 32 + ci + 1];
            float  eg = sf[bo + SC_EB / 4 + tt * 2];
            float  bt = sf[bo + SC_EB / 4 + tt * 2 + 1];
            float  xq = sf[bo + SC_XB / 4 + tt];

            float dkA = k0.x*SaA.x + k0.y*SaA.y + k0.z*SaA.z + k0.w*SaA.w
                      + k1.x*SbA.x + k1.y*SbA.y + k1.z*SbA.z + k1.w*SbA.w;
            float dqA = q0.x*SaA.x + q0.y*SaA.y + q0.z*SaA.z + q0.w*SaA.w
                      + q1.x*SbA.x + q1.y*SbA.y + q1.z*SbA.z + q1.w*SbA.w;
            float dkB = k0.x*SaB.x + k0.y*SaB.y + k0.z*SaB.z + k0.w*SaB.w
                      + k1.x*SbB.x + k1.y*SbB.y + k1.z*SbB.z + k1.w*SbB.w;
            float dqB = q0.x*SaB.x + q0.y*SaB.y + q0.z*SaB.z + q0.w*SaB.w
                      + q1.x*SbB.x + q1.y*SbB.y + q1.z*SbB.z + q1.w*SbB.w;
#pragma unroll
            for (int off = 8; off > 0; off >>= 1) {
                dkA += __shfl_xor_sync(0xffffffffu, dkA, off);
                dkB += __shfl_xor_sync(0xffffffffu, dkB, off);
                dqA += __shfl_xor_sync(0xffffffffu, dqA, off);
                dqB += __shfl_xor_sync(0xffffffffu, dqB, off);
            }
            const float deltaA = (vtA - eg * dkA) * bt;
            const float deltaB = (vtB - eg * dkB) * bt;
            const float otA    = fmaf(eg, dqA, xq * deltaA);
            const float otB    = fmaf(eg, dqB, xq * deltaB);
            SaA.x = fmaf(SaA.x, eg, k0.x * deltaA);
            SaA.y = fmaf(SaA.y, eg, k0.y * deltaA);
            SaA.z = fmaf(SaA.z, eg, k0.z * deltaA);
            SaA.w = fmaf(SaA.w, eg, k0.w * deltaA);
            SbA.x = fmaf(SbA.x, eg, k1.x * deltaA);
            SbA.y = fmaf(SbA.y, eg, k1.y * deltaA);
            SbA.z = fmaf(SbA.z, eg, k1.z * deltaA);
            SbA.w = fmaf(SbA.w, eg, k1.w * deltaA);
            SaB.x = fmaf(SaB.x, eg, k0.x * deltaB);
            SaB.y = fmaf(SaB.y, eg, k0.y * deltaB);
            SaB.z = fmaf(SaB.z, eg, k0.z * deltaB);
            SaB.w = fmaf(SaB.w, eg, k0.w * deltaB);
            SbB.x = fmaf(SbB.x, eg, k1.x * deltaB);
            SbB.y = fmaf(SbB.y, eg, k1.y * deltaB);
            SbB.z = fmaf(SbB.z, eg, k1.z * deltaB);
            SbB.w = fmaf(SbB.w, eg, k1.w * deltaB);
            if (sl == 0)
                *(float2*)&op[(size_t)(c * SC_TC + tt) * VAL_DIM] = make_float2(otA, otB);
        }
        __syncthreads();
    }
}

// ---------------- RMSNorm * norm_w * silu(z), write fp16 directly ----------------
__global__ __launch_bounds__(256) void rms_gate_half(
    const float* __restrict__ o, const float* __restrict__ qkvz,
    const float* __restrict__ norm_w, __half* __restrict__ hi)
{
    int gid  = blockIdx.x * 8 + (threadIdx.x >> 5);
    int lane = threadIdx.x & 31;
    int t = gid >> 5;
    int h = gid & 31;
    const float* orow = o + (size_t)t * VAL_DIM + h * DV;
    float4 x = *(const float4*)(orow + lane * 4);
    float s = x.x * x.x + x.y * x.y + x.z * x.z + x.w * x.w;
#pragma unroll
    for (int off = 16; off > 0; off >>= 1) s += __shfl_xor_sync(0xffffffffu, s, off);
    float r = rsqrtf(s * (1.0f / DV) + 1e-6f);
    float4 z  = *(const float4*)(qkvz + (size_t)t * QKVZ_N + 2 * KEY_DIM + VAL_DIM + h * DV + lane * 4);
    float4 nw = *(const float4*)(norm_w + lane * 4);
    float4 y;
    y.x = x.x * r * nw.x * siluf_(z.x);
    y.y = x.y * r * nw.y * siluf_(z.y);
    y.z = x.z * r * nw.z * siluf_(z.z);
    y.w = x.w * r * nw.w * siluf_(z.w);
    union { __half2 h2v[2]; uint2 u; } H;
    H.h2v[0] = __halves2half2(__float2half_rn(y.x), __float2half_rn(y.y));
    H.h2v[1] = __halves2half2(__float2half_rn(y.z), __float2half_rn(y.w));
    int i4 = (t * VAL_DIM + h * DV) / 4 + lane;
    ((uint2*)hi)[i4] = H.u;
}

// ---------------- launch ----------------
extern "C" void kernel_launch(void* const* d_in, const int* in_sizes, int n_in,
                              void* d_out, int out_size)
{
    const float* h_in    = (const float*)d_in[0];
    const float* W_qkvz  = (const float*)d_in[1];
    const float* W_ba    = (const float*)d_in[2];
    const float* conv_w  = (const float*)d_in[3];
    const float* dt_bias = (const float*)d_in[4];
    const float* A_log   = (const float*)d_in[5];
    const float* norm_w  = (const float*)d_in[6];
    const float* W_out   = (const float*)d_in[7];
    float* out = (float*)d_out;

    float *qkvz, *qkv, *ba, *qhat, *khat, *qkdot, *oscan;
    float2* egbeta;
    __half *Wq, *Wo, *A_hi;
    cudaGetSymbolAddress((void**)&qkvz,   g_qkvz);
    cudaGetSymbolAddress((void**)&qkv,    g_qkv);
    cudaGetSymbolAddress((void**)&ba,     g_ba);
    cudaGetSymbolAddress((void**)&egbeta, g_egbeta);
    cudaGetSymbolAddress((void**)&qhat,   g_qhat);
    cudaGetSymbolAddress((void**)&khat,   g_khat);
    cudaGetSymbolAddress((void**)&qkdot,  g_qkdot);
    cudaGetSymbolAddress((void**)&oscan,  g_oscan);
    cudaGetSymbolAddress((void**)&Wq,     g_Wq);
    cudaGetSymbolAddress((void**)&Wo,     g_Wo);
    cudaGetSymbolAddress((void**)&A_hi,   g_A_hi);

    cudaFuncSetAttribute(gemm_tc, cudaFuncAttributeMaxDynamicSharedMemorySize, GT_SMEM);
    cudaFuncSetAttribute(gdn_scan, cudaFuncAttributeMaxDynamicSharedMemorySize, SC_SMEM);

    // prep
    {
        dim3 blk(32, 8);
        tr_half<<<dim3(QKVZ_N / 32, HID / 32), blk>>>(W_qkvz, Wq, HID, QKVZ_N);
        tr_half<<<dim3(HID / 32, VAL_DIM / 32), blk>>>(W_out, Wo, VAL_DIM, HID);
    }
    cvt_half<<<(T_SEQ * HID / 4 + 255) / 256, 256>>>(h_in, A_hi, T_SEQ * HID / 4);

    // GEMM1: qkvz = h @ W_qkvz   [2048 x 12288], K=2048
    gemm_tc<<<dim3(T_SEQ / 128, QKVZ_N / 128), 256, GT_SMEM>>>(A_hi, Wq, qkvz, QKVZ_N, HID);

    gemm_ba<<<T_SEQ / 64, 256>>>(h_in, W_ba, ba);
    conv_silu<<<((T_SEQ / 4) * CONV_DIM) / 256, 256>>>(qkvz, conv_w, qkv);
    gate_prep<<<(T_SEQ * NUM_V) / 256, 256>>>(ba, A_log, dt_bias, egbeta);
    l2norm_qk_dot<<<(T_SEQ * NUM_K) / 8, 256>>>(qkv, qhat, khat, qkdot);
    gdn_scan<<<NUM_V * 4, 256, SC_SMEM>>>(qhat, khat, qkv, (const float*)egbeta, qkdot, oscan);
    rms_gate_half<<<(T_SEQ * NUM_V) / 8, 256>>>(oscan, qkvz, norm_w, A_hi);

    // GEMM2: out = gated @ W_out  [2048 x 2048], K=4096
    gemm_tc<<<dim3(T_SEQ / 128, HID / 128), 256, GT_SMEM>>>(A_hi, Wo, out, HID, VAL_DIM);
}